// round 1
// baseline (speedup 1.0000x reference)
#include <cuda_runtime.h>

#define Bn 2
#define Sn 2048
#define Dn 1024
#define Hn 16
#define HDn 64
#define Mn (Bn*Sn)
#define TQ 64
#define TK 64
#define ATT_SCALE 0.125f   /* 64^-0.5 */

static __device__ float g_q[(size_t)Mn*Dn];
static __device__ float g_k[(size_t)Mn*Dn];
static __device__ float g_v[(size_t)Mn*Dn];
static __device__ float g_ao[(size_t)Mn*Dn];

// ---------------------------------------------------------------------------
// 128x128x8 tiled SGEMM: C[M,N] = A[M,K] @ W[N,K]^T + bias[N]
// 256 threads, 8x8 per-thread micro tile.
// ---------------------------------------------------------------------------
__global__ __launch_bounds__(256) void sgemm128(const float* __restrict__ A,
    const float* __restrict__ W, const float* __restrict__ bias,
    float* __restrict__ C, int M, int N, int K)
{
    __shared__ float As[8][128];
    __shared__ float Bs[8][128];
    const int m0 = blockIdx.y * 128, n0 = blockIdx.x * 128;
    const int tid = threadIdx.x;
    const int tx = tid & 15, ty = tid >> 4;
    float acc[8][8] = {};

    const int lrow = tid >> 1;
    const int lseg = (tid & 1) * 4;
    const float* Ap = A + (size_t)(m0 + lrow) * K + lseg;
    const float* Wp = W + (size_t)(n0 + lrow) * K + lseg;

    for (int kt = 0; kt < K; kt += 8) {
        float4 av = *(const float4*)(Ap + kt);
        float4 wv = *(const float4*)(Wp + kt);
        As[lseg + 0][lrow] = av.x; As[lseg + 1][lrow] = av.y;
        As[lseg + 2][lrow] = av.z; As[lseg + 3][lrow] = av.w;
        Bs[lseg + 0][lrow] = wv.x; Bs[lseg + 1][lrow] = wv.y;
        Bs[lseg + 2][lrow] = wv.z; Bs[lseg + 3][lrow] = wv.w;
        __syncthreads();
#pragma unroll
        for (int kk = 0; kk < 8; kk++) {
            float4 a0 = *(const float4*)&As[kk][ty * 8];
            float4 a1 = *(const float4*)&As[kk][ty * 8 + 4];
            float4 b0 = *(const float4*)&Bs[kk][tx * 8];
            float4 b1 = *(const float4*)&Bs[kk][tx * 8 + 4];
            float a[8] = {a0.x, a0.y, a0.z, a0.w, a1.x, a1.y, a1.z, a1.w};
            float b[8] = {b0.x, b0.y, b0.z, b0.w, b1.x, b1.y, b1.z, b1.w};
#pragma unroll
            for (int i = 0; i < 8; i++)
#pragma unroll
                for (int j = 0; j < 8; j++)
                    acc[i][j] += a[i] * b[j];
        }
        __syncthreads();
    }

    float bv[8];
#pragma unroll
    for (int j = 0; j < 8; j++) bv[j] = bias[n0 + tx * 8 + j];
#pragma unroll
    for (int i = 0; i < 8; i++) {
        float* Cr = C + (size_t)(m0 + ty * 8 + i) * N + n0 + tx * 8;
#pragma unroll
        for (int j = 0; j < 8; j++) Cr[j] = acc[i][j] + bv[j];
    }
}

// ---------------------------------------------------------------------------
// Flash-style attention with document-block mask + KV-range skipping.
// One block per (q-tile of 64, head, batch). 256 threads (16x16, 4x4 micro).
// ---------------------------------------------------------------------------
__global__ __launch_bounds__(256) void attn_kernel(const float* __restrict__ gq,
    const float* __restrict__ gk, const float* __restrict__ gv,
    const int* __restrict__ doc, float* __restrict__ gout)
{
    extern __shared__ float sm[];
    float (*Qs)[HDn + 1] = (float(*)[HDn + 1])sm;                          // 64x65
    float (*Ks)[HDn + 1] = (float(*)[HDn + 1])(sm + TQ * (HDn + 1));      // 64x65
    float (*Sc)[TK + 1]  = (float(*)[TK + 1]) (sm + 2 * TQ * (HDn + 1));  // 64x65
    float (*Vs)[HDn]     = (float(*)[HDn])    (sm + 2 * TQ * (HDn + 1) + TQ * (TK + 1)); // 64x64
    __shared__ float m_s[TQ], l_s[TQ], f_s[TQ];
    __shared__ int qdoc[TQ], kdoc[TK], srange[2];

    const int q0 = blockIdx.x * TQ;
    const int h = blockIdx.y, b = blockIdx.z;
    const int tid = threadIdx.x;
    const int tx = tid & 15, ty = tid >> 4;

    if (tid == 0) { srange[0] = Sn; srange[1] = 0; }
    if (tid < TQ) { qdoc[tid] = doc[q0 + tid]; m_s[tid] = -3.4e38f; l_s[tid] = 0.f; }
    __syncthreads();
    const int dlo = qdoc[0], dhi = qdoc[TQ - 1];
    for (int i = tid; i < Sn; i += 256) {
        int di = doc[i];
        if (di == dlo) atomicMin(&srange[0], i);
        if (di == dhi) atomicMax(&srange[1], i);
    }
    const size_t baseq = ((size_t)(b * Sn + q0)) * Dn + h * HDn;
    for (int e = tid; e < TQ * HDn; e += 256) {
        int q = e >> 6, d = e & 63;
        Qs[q][d] = gq[baseq + (size_t)q * Dn + d];
    }
    __syncthreads();
    const int kv_begin = (srange[0] / TK) * TK;
    const int kv_end   = srange[1] + 1;

    float O[4][4] = {};
    for (int k0 = kv_begin; k0 < kv_end; k0 += TK) {
        const size_t basek = ((size_t)(b * Sn + k0)) * Dn + h * HDn;
        for (int e = tid; e < TK * HDn; e += 256) {
            int k = e >> 6, d = e & 63;
            float kvk = gk[basek + (size_t)k * Dn + d];
            float kvv = gv[basek + (size_t)k * Dn + d];
            Ks[k][d] = kvk;
            Vs[k][d] = kvv;
        }
        if (tid < TK) kdoc[tid] = doc[k0 + tid];
        __syncthreads();

        // scores: Sc = (Qs @ Ks^T) * scale, with document mask
        float c[4][4] = {};
#pragma unroll
        for (int d = 0; d < HDn; d++) {
            float a[4], bb[4];
#pragma unroll
            for (int i = 0; i < 4; i++) a[i] = Qs[ty * 4 + i][d];
#pragma unroll
            for (int j = 0; j < 4; j++) bb[j] = Ks[tx * 4 + j][d];
#pragma unroll
            for (int i = 0; i < 4; i++)
#pragma unroll
                for (int j = 0; j < 4; j++) c[i][j] += a[i] * bb[j];
        }
#pragma unroll
        for (int i = 0; i < 4; i++) {
            int qd = qdoc[ty * 4 + i];
#pragma unroll
            for (int j = 0; j < 4; j++)
                Sc[ty * 4 + i][tx * 4 + j] =
                    (qd == kdoc[tx * 4 + j]) ? c[i][j] * ATT_SCALE : -1e30f;
        }
        __syncthreads();

        // online softmax: 4 threads per row
        {
            const int r = tid >> 2, p = tid & 3;
            float mx = -3.4e38f;
#pragma unroll
            for (int e = 0; e < 16; e++) mx = fmaxf(mx, Sc[r][p * 16 + e]);
            mx = fmaxf(mx, __shfl_xor_sync(0xffffffffu, mx, 1));
            mx = fmaxf(mx, __shfl_xor_sync(0xffffffffu, mx, 2));
            const float mo = m_s[r];
            const float mn = fmaxf(mo, mx);
            float ps = 0.f;
#pragma unroll
            for (int e = 0; e < 16; e++) {
                float s = Sc[r][p * 16 + e];
                float pe = (s < -1e29f) ? 0.f : __expf(s - mn);
                Sc[r][p * 16 + e] = pe;
                ps += pe;
            }
            ps += __shfl_xor_sync(0xffffffffu, ps, 1);
            ps += __shfl_xor_sync(0xffffffffu, ps, 2);
            if (p == 0) {
                f_s[r] = __expf(mo - mn);
                l_s[r] = l_s[r] * f_s[r] + ps;
                m_s[r] = mn;
            }
        }
        __syncthreads();

        // rescale running O, then O += P @ V
#pragma unroll
        for (int i = 0; i < 4; i++) {
            float fi = f_s[ty * 4 + i];
#pragma unroll
            for (int j = 0; j < 4; j++) O[i][j] *= fi;
        }
#pragma unroll
        for (int kk = 0; kk < TK; kk++) {
            float a[4], bb[4];
#pragma unroll
            for (int i = 0; i < 4; i++) a[i] = Sc[ty * 4 + i][kk];
#pragma unroll
            for (int j = 0; j < 4; j++) bb[j] = Vs[kk][tx * 4 + j];
#pragma unroll
            for (int i = 0; i < 4; i++)
#pragma unroll
                for (int j = 0; j < 4; j++) O[i][j] += a[i] * bb[j];
        }
        __syncthreads();
    }

#pragma unroll
    for (int i = 0; i < 4; i++) {
        float inv = 1.f / l_s[ty * 4 + i];
        float* orow = gout + baseq + (size_t)(ty * 4 + i) * Dn + tx * 4;
#pragma unroll
        for (int j = 0; j < 4; j++) orow[j] = O[i][j] * inv;
    }
}

// ---------------------------------------------------------------------------
extern "C" void kernel_launch(void* const* d_in, const int* in_sizes, int n_in,
                              void* d_out, int out_size)
{
    (void)in_sizes; (void)n_in; (void)out_size;
    const float* x  = (const float*)d_in[0];
    const float* wq = (const float*)d_in[1];
    const float* bq = (const float*)d_in[2];
    const float* wk = (const float*)d_in[3];
    const float* bk = (const float*)d_in[4];
    const float* wv = (const float*)d_in[5];
    const float* bv = (const float*)d_in[6];
    const float* wo = (const float*)d_in[7];
    const float* bo = (const float*)d_in[8];
    const int*  doc = (const int*)d_in[9];
    float* out = (float*)d_out;

    float *qp, *kp, *vp, *aop;
    cudaGetSymbolAddress((void**)&qp, g_q);
    cudaGetSymbolAddress((void**)&kp, g_k);
    cudaGetSymbolAddress((void**)&vp, g_v);
    cudaGetSymbolAddress((void**)&aop, g_ao);

    dim3 gg(Dn / 128, Mn / 128);
    sgemm128<<<gg, 256>>>(x, wq, bq, qp, Mn, Dn, Dn);
    sgemm128<<<gg, 256>>>(x, wk, bk, kp, Mn, Dn, Dn);
    sgemm128<<<gg, 256>>>(x, wv, bv, vp, Mn, Dn, Dn);

    const int smem_bytes = (2 * TQ * (HDn + 1) + TQ * (TK + 1) + TK * HDn) * (int)sizeof(float);
    cudaFuncSetAttribute(attn_kernel, cudaFuncAttributeMaxDynamicSharedMemorySize, smem_bytes);
    dim3 ga(Sn / TQ, Hn, Bn);
    attn_kernel<<<ga, 256, smem_bytes>>>(qp, kp, vp, doc, aop);

    sgemm128<<<gg, 256>>>(aop, wo, bo, out, Mn, Dn, Dn);
}

// round 2
// speedup vs baseline: 1.3779x; 1.3779x over previous
#include <cuda_runtime.h>
#include <cstdint>

#define Bn 2
#define Sn 2048
#define Dn 1024
#define Hn 16
#define HDn 64
#define Mn (Bn*Sn)
#define TQ 64
#define TK 64
#define ATT_SCALE 0.125f   /* 64^-0.5 */

static __device__ float g_q[(size_t)Mn*Dn];
static __device__ float g_k[(size_t)Mn*Dn];
static __device__ float g_v[(size_t)Mn*Dn];
static __device__ float g_ao[(size_t)Mn*Dn];

// ---------------------------------------------------------------------------
// 3xTF32 tensor-core GEMM: C[M,N] = A[M,K] @ W[N,K]^T + bias[N]
// Block 128x128, KT=32. 8 warps (4 along M x 2 along N), each warp 32x64.
// mma.sync.m16n8k8.tf32 with hi/lo split: AhBh + AhBl + AlBh (~fp32 accuracy).
// ---------------------------------------------------------------------------
#define KT 32
#define ASTR 36   /* smem row stride in floats: 32 + 4 pad -> conflict-free frags */

__device__ __forceinline__ uint32_t f2tf(float x) {
    uint32_t r;
    asm("cvt.rna.tf32.f32 %0, %1;" : "=r"(r) : "f"(x));
    return r;
}

__device__ __forceinline__ void mma8(float* d, const uint32_t* a,
                                     uint32_t b0, uint32_t b1) {
    asm volatile(
        "mma.sync.aligned.m16n8k8.row.col.f32.tf32.tf32.f32 "
        "{%0,%1,%2,%3},{%4,%5,%6,%7},{%8,%9},{%0,%1,%2,%3};"
        : "+f"(d[0]), "+f"(d[1]), "+f"(d[2]), "+f"(d[3])
        : "r"(a[0]), "r"(a[1]), "r"(a[2]), "r"(a[3]), "r"(b0), "r"(b1));
}

__global__ __launch_bounds__(256) void gemm_tf32(const float* __restrict__ A,
    const float* __restrict__ W, const float* __restrict__ bias,
    float* __restrict__ C, int M, int N, int K)
{
    extern __shared__ float sm[];
    float* Ah = sm;                      // [128][ASTR]
    float* Al = Ah + 128 * ASTR;
    float* Bh = Al + 128 * ASTR;
    float* Bl = Bh + 128 * ASTR;

    const int m0 = blockIdx.y * 128, n0 = blockIdx.x * 128;
    const int tid = threadIdx.x;
    const int lane = tid & 31, wid = tid >> 5;
    const int g = lane >> 2, t = lane & 3;
    const int mBase = (wid & 3) * 32;
    const int nBase = (wid >> 2) * 64;

    float acc[2][8][4];
#pragma unroll
    for (int i = 0; i < 2; i++)
#pragma unroll
        for (int j = 0; j < 8; j++)
#pragma unroll
            for (int l = 0; l < 4; l++) acc[i][j][l] = 0.f;

    const int lrow = tid >> 3;          // 0..31
    const int lk = (tid & 7) * 4;       // 0,4,...,28

    for (int kt = 0; kt < K; kt += KT) {
#pragma unroll
        for (int p = 0; p < 4; p++) {
            int row = lrow + p * 32;
            float4 av = *(const float4*)(A + (size_t)(m0 + row) * K + kt + lk);
            float4 wv = *(const float4*)(W + (size_t)(n0 + row) * K + kt + lk);
            float ahx = __uint_as_float(f2tf(av.x));
            float ahy = __uint_as_float(f2tf(av.y));
            float ahz = __uint_as_float(f2tf(av.z));
            float ahw = __uint_as_float(f2tf(av.w));
            float whx = __uint_as_float(f2tf(wv.x));
            float why = __uint_as_float(f2tf(wv.y));
            float whz = __uint_as_float(f2tf(wv.z));
            float whw = __uint_as_float(f2tf(wv.w));
            float* ahp = Ah + row * ASTR + lk;
            float* alp = Al + row * ASTR + lk;
            float* bhp = Bh + row * ASTR + lk;
            float* blp = Bl + row * ASTR + lk;
            ahp[0] = ahx; ahp[1] = ahy; ahp[2] = ahz; ahp[3] = ahw;
            alp[0] = __uint_as_float(f2tf(av.x - ahx));
            alp[1] = __uint_as_float(f2tf(av.y - ahy));
            alp[2] = __uint_as_float(f2tf(av.z - ahz));
            alp[3] = __uint_as_float(f2tf(av.w - ahw));
            bhp[0] = whx; bhp[1] = why; bhp[2] = whz; bhp[3] = whw;
            blp[0] = __uint_as_float(f2tf(wv.x - whx));
            blp[1] = __uint_as_float(f2tf(wv.y - why));
            blp[2] = __uint_as_float(f2tf(wv.z - whz));
            blp[3] = __uint_as_float(f2tf(wv.w - whw));
        }
        __syncthreads();

#pragma unroll
        for (int k8 = 0; k8 < KT; k8 += 8) {
            uint32_t ah[2][4], al[2][4];
#pragma unroll
            for (int mt = 0; mt < 2; mt++) {
                int r = mBase + mt * 16 + g;
                ah[mt][0] = __float_as_uint(Ah[r * ASTR + k8 + t]);
                ah[mt][1] = __float_as_uint(Ah[(r + 8) * ASTR + k8 + t]);
                ah[mt][2] = __float_as_uint(Ah[r * ASTR + k8 + t + 4]);
                ah[mt][3] = __float_as_uint(Ah[(r + 8) * ASTR + k8 + t + 4]);
                al[mt][0] = __float_as_uint(Al[r * ASTR + k8 + t]);
                al[mt][1] = __float_as_uint(Al[(r + 8) * ASTR + k8 + t]);
                al[mt][2] = __float_as_uint(Al[r * ASTR + k8 + t + 4]);
                al[mt][3] = __float_as_uint(Al[(r + 8) * ASTR + k8 + t + 4]);
            }
#pragma unroll
            for (int nt = 0; nt < 8; nt++) {
                int n = nBase + nt * 8 + g;
                uint32_t bh0 = __float_as_uint(Bh[n * ASTR + k8 + t]);
                uint32_t bh1 = __float_as_uint(Bh[n * ASTR + k8 + t + 4]);
                uint32_t bl0 = __float_as_uint(Bl[n * ASTR + k8 + t]);
                uint32_t bl1 = __float_as_uint(Bl[n * ASTR + k8 + t + 4]);
#pragma unroll
                for (int mt = 0; mt < 2; mt++) {
                    mma8(acc[mt][nt], ah[mt], bh0, bh1);   // hi*hi
                    mma8(acc[mt][nt], ah[mt], bl0, bl1);   // hi*lo
                    mma8(acc[mt][nt], al[mt], bh0, bh1);   // lo*hi
                }
            }
        }
        __syncthreads();
    }

#pragma unroll
    for (int mt = 0; mt < 2; mt++) {
        int r0 = m0 + mBase + mt * 16 + g;
#pragma unroll
        for (int nt = 0; nt < 8; nt++) {
            int c = n0 + nBase + nt * 8 + 2 * t;
            float b0v = bias[c], b1v = bias[c + 1];
            *(float2*)&C[(size_t)r0 * N + c] =
                make_float2(acc[mt][nt][0] + b0v, acc[mt][nt][1] + b1v);
            *(float2*)&C[(size_t)(r0 + 8) * N + c] =
                make_float2(acc[mt][nt][2] + b0v, acc[mt][nt][3] + b1v);
        }
    }
}

// ---------------------------------------------------------------------------
// Flash-style attention with document-block mask + KV-range skipping.
// One block per (q-tile of 64, head, batch). 256 threads (16x16, 4x4 micro).
// ---------------------------------------------------------------------------
__global__ __launch_bounds__(256) void attn_kernel(const float* __restrict__ gq,
    const float* __restrict__ gk, const float* __restrict__ gv,
    const int* __restrict__ doc, float* __restrict__ gout)
{
    extern __shared__ float sm[];
    float (*Qs)[HDn + 1] = (float(*)[HDn + 1])sm;                          // 64x65
    float (*Ks)[HDn + 1] = (float(*)[HDn + 1])(sm + TQ * (HDn + 1));      // 64x65
    float (*Sc)[TK + 1]  = (float(*)[TK + 1]) (sm + 2 * TQ * (HDn + 1));  // 64x65
    float (*Vs)[HDn]     = (float(*)[HDn])    (sm + 2 * TQ * (HDn + 1) + TQ * (TK + 1)); // 64x64
    __shared__ float m_s[TQ], l_s[TQ], f_s[TQ];
    __shared__ int qdoc[TQ], kdoc[TK], srange[2];

    const int q0 = blockIdx.x * TQ;
    const int h = blockIdx.y, b = blockIdx.z;
    const int tid = threadIdx.x;
    const int tx = tid & 15, ty = tid >> 4;

    if (tid == 0) { srange[0] = Sn; srange[1] = 0; }
    if (tid < TQ) { qdoc[tid] = doc[q0 + tid]; m_s[tid] = -3.4e38f; l_s[tid] = 0.f; }
    __syncthreads();
    const int dlo = qdoc[0], dhi = qdoc[TQ - 1];
    for (int i = tid; i < Sn; i += 256) {
        int di = doc[i];
        if (di == dlo) atomicMin(&srange[0], i);
        if (di == dhi) atomicMax(&srange[1], i);
    }
    const size_t baseq = ((size_t)(b * Sn + q0)) * Dn + h * HDn;
    for (int e = tid; e < TQ * HDn; e += 256) {
        int q = e >> 6, d = e & 63;
        Qs[q][d] = gq[baseq + (size_t)q * Dn + d];
    }
    __syncthreads();
    const int kv_begin = (srange[0] / TK) * TK;
    const int kv_end   = srange[1] + 1;

    float O[4][4] = {};
    for (int k0 = kv_begin; k0 < kv_end; k0 += TK) {
        const size_t basek = ((size_t)(b * Sn + k0)) * Dn + h * HDn;
        for (int e = tid; e < TK * HDn; e += 256) {
            int k = e >> 6, d = e & 63;
            Ks[k][d] = gk[basek + (size_t)k * Dn + d];
            Vs[k][d] = gv[basek + (size_t)k * Dn + d];
        }
        if (tid < TK) kdoc[tid] = doc[k0 + tid];
        __syncthreads();

        float c[4][4] = {};
#pragma unroll
        for (int d = 0; d < HDn; d++) {
            float a[4], bb[4];
#pragma unroll
            for (int i = 0; i < 4; i++) a[i] = Qs[ty * 4 + i][d];
#pragma unroll
            for (int j = 0; j < 4; j++) bb[j] = Ks[tx * 4 + j][d];
#pragma unroll
            for (int i = 0; i < 4; i++)
#pragma unroll
                for (int j = 0; j < 4; j++) c[i][j] += a[i] * bb[j];
        }
#pragma unroll
        for (int i = 0; i < 4; i++) {
            int qd = qdoc[ty * 4 + i];
#pragma unroll
            for (int j = 0; j < 4; j++)
                Sc[ty * 4 + i][tx * 4 + j] =
                    (qd == kdoc[tx * 4 + j]) ? c[i][j] * ATT_SCALE : -1e30f;
        }
        __syncthreads();

        {
            const int r = tid >> 2, p = tid & 3;
            float mx = -3.4e38f;
#pragma unroll
            for (int e = 0; e < 16; e++) mx = fmaxf(mx, Sc[r][p * 16 + e]);
            mx = fmaxf(mx, __shfl_xor_sync(0xffffffffu, mx, 1));
            mx = fmaxf(mx, __shfl_xor_sync(0xffffffffu, mx, 2));
            const float mo = m_s[r];
            const float mn = fmaxf(mo, mx);
            float ps = 0.f;
#pragma unroll
            for (int e = 0; e < 16; e++) {
                float s = Sc[r][p * 16 + e];
                float pe = (s < -1e29f) ? 0.f : __expf(s - mn);
                Sc[r][p * 16 + e] = pe;
                ps += pe;
            }
            ps += __shfl_xor_sync(0xffffffffu, ps, 1);
            ps += __shfl_xor_sync(0xffffffffu, ps, 2);
            if (p == 0) {
                f_s[r] = __expf(mo - mn);
                l_s[r] = l_s[r] * f_s[r] + ps;
                m_s[r] = mn;
            }
        }
        __syncthreads();

#pragma unroll
        for (int i = 0; i < 4; i++) {
            float fi = f_s[ty * 4 + i];
#pragma unroll
            for (int j = 0; j < 4; j++) O[i][j] *= fi;
        }
#pragma unroll
        for (int kk = 0; kk < TK; kk++) {
            float a[4], bb[4];
#pragma unroll
            for (int i = 0; i < 4; i++) a[i] = Sc[ty * 4 + i][kk];
#pragma unroll
            for (int j = 0; j < 4; j++) bb[j] = Vs[kk][tx * 4 + j];
#pragma unroll
            for (int i = 0; i < 4; i++)
#pragma unroll
                for (int j = 0; j < 4; j++) O[i][j] += a[i] * bb[j];
        }
        __syncthreads();
    }

#pragma unroll
    for (int i = 0; i < 4; i++) {
        float inv = 1.f / l_s[ty * 4 + i];
        float* orow = gout + baseq + (size_t)(ty * 4 + i) * Dn + tx * 4;
#pragma unroll
        for (int j = 0; j < 4; j++) orow[j] = O[i][j] * inv;
    }
}

// ---------------------------------------------------------------------------
extern "C" void kernel_launch(void* const* d_in, const int* in_sizes, int n_in,
                              void* d_out, int out_size)
{
    (void)in_sizes; (void)n_in; (void)out_size;
    const float* x  = (const float*)d_in[0];
    const float* wq = (const float*)d_in[1];
    const float* bq = (const float*)d_in[2];
    const float* wk = (const float*)d_in[3];
    const float* bk = (const float*)d_in[4];
    const float* wv = (const float*)d_in[5];
    const float* bv = (const float*)d_in[6];
    const float* wo = (const float*)d_in[7];
    const float* bo = (const float*)d_in[8];
    const int*  doc = (const int*)d_in[9];
    float* out = (float*)d_out;

    float *qp, *kp, *vp, *aop;
    cudaGetSymbolAddress((void**)&qp, g_q);
    cudaGetSymbolAddress((void**)&kp, g_k);
    cudaGetSymbolAddress((void**)&vp, g_v);
    cudaGetSymbolAddress((void**)&aop, g_ao);

    const int gemm_smem = 4 * 128 * ASTR * (int)sizeof(float);  // 73728
    cudaFuncSetAttribute(gemm_tf32, cudaFuncAttributeMaxDynamicSharedMemorySize, gemm_smem);

    dim3 gg(Dn / 128, Mn / 128);
    gemm_tf32<<<gg, 256, gemm_smem>>>(x, wq, bq, qp, Mn, Dn, Dn);
    gemm_tf32<<<gg, 256, gemm_smem>>>(x, wk, bk, kp, Mn, Dn, Dn);
    gemm_tf32<<<gg, 256, gemm_smem>>>(x, wv, bv, vp, Mn, Dn, Dn);

    const int attn_smem = (2 * TQ * (HDn + 1) + TQ * (TK + 1) + TK * HDn) * (int)sizeof(float);
    cudaFuncSetAttribute(attn_kernel, cudaFuncAttributeMaxDynamicSharedMemorySize, attn_smem);
    dim3 ga(Sn / TQ, Hn, Bn);
    attn_kernel<<<ga, 256, attn_smem>>>(qp, kp, vp, doc, aop);

    gemm_tf32<<<gg, 256, gemm_smem>>>(aop, wo, bo, out, Mn, Dn, Dn);
}

// round 4
// speedup vs baseline: 2.1984x; 1.5955x over previous
#include <cuda_runtime.h>
#include <cuda_bf16.h>
#include <cstdint>

#define Bn 2
#define Sn 2048
#define Dn 1024
#define Hn 16
#define HDn 64
#define Mn (Bn*Sn)
#define TQ 64
#define TK 64
#define ATT_SCALE 0.125f   /* 64^-0.5 */

// fp32 intermediates for attention
static __device__ float g_q[(size_t)Mn*Dn];
static __device__ float g_k[(size_t)Mn*Dn];
static __device__ float g_v[(size_t)Mn*Dn];
// bf16 hi/lo splits
static __device__ __nv_bfloat16 g_xh[(size_t)Mn*Dn],  g_xl[(size_t)Mn*Dn];
static __device__ __nv_bfloat16 g_wqh[(size_t)Dn*Dn], g_wql[(size_t)Dn*Dn];
static __device__ __nv_bfloat16 g_wkh[(size_t)Dn*Dn], g_wkl[(size_t)Dn*Dn];
static __device__ __nv_bfloat16 g_wvh[(size_t)Dn*Dn], g_wvl[(size_t)Dn*Dn];
static __device__ __nv_bfloat16 g_woh[(size_t)Dn*Dn], g_wol[(size_t)Dn*Dn];
static __device__ __nv_bfloat16 g_aoh[(size_t)Mn*Dn], g_aol[(size_t)Mn*Dn];

// ---------------------------------------------------------------------------
// Split fp32 -> bf16 hi + bf16 lo (residual). Vectorized by 4.
// ---------------------------------------------------------------------------
__global__ __launch_bounds__(256) void split_bf16(const float4* __restrict__ src,
    __nv_bfloat162* __restrict__ hi, __nv_bfloat162* __restrict__ lo, int n4)
{
    int i = blockIdx.x * 256 + threadIdx.x;
    if (i >= n4) return;
    float4 v = src[i];
    __nv_bfloat16 hx = __float2bfloat16_rn(v.x);
    __nv_bfloat16 hy = __float2bfloat16_rn(v.y);
    __nv_bfloat16 hz = __float2bfloat16_rn(v.z);
    __nv_bfloat16 hw = __float2bfloat16_rn(v.w);
    hi[2 * i]     = __nv_bfloat162(hx, hy);
    hi[2 * i + 1] = __nv_bfloat162(hz, hw);
    lo[2 * i]     = __nv_bfloat162(__float2bfloat16_rn(v.x - __bfloat162float(hx)),
                                   __float2bfloat16_rn(v.y - __bfloat162float(hy)));
    lo[2 * i + 1] = __nv_bfloat162(__float2bfloat16_rn(v.z - __bfloat162float(hz)),
                                   __float2bfloat16_rn(v.w - __bfloat162float(hw)));
}

// ---------------------------------------------------------------------------
// 3xBF16 tensor-core GEMM: C[M,N] = A @ W^T + bias, A/W pre-split hi/lo bf16.
// Block 128x128, KT=32, cp.async double-buffered. 8 warps, warp tile 32x64.
// mma.sync.m16n8k16.bf16: AhBh + AhBl + AlBh.
// ---------------------------------------------------------------------------
#define KT 32
#define PAD 40                 /* bf16 row stride: 32 + 8 pad, conflict-free */
#define STAGE (128 * PAD)      /* bf16 elems per array per stage */

__device__ __forceinline__ void mma16(float* d, const uint32_t* a,
                                      uint32_t b0, uint32_t b1) {
    asm volatile(
        "mma.sync.aligned.m16n8k16.row.col.f32.bf16.bf16.f32 "
        "{%0,%1,%2,%3},{%4,%5,%6,%7},{%8,%9},{%0,%1,%2,%3};"
        : "+f"(d[0]), "+f"(d[1]), "+f"(d[2]), "+f"(d[3])
        : "r"(a[0]), "r"(a[1]), "r"(a[2]), "r"(a[3]), "r"(b0), "r"(b1));
}

__device__ __forceinline__ void cp16(uint32_t s, const void* g) {
    asm volatile("cp.async.cg.shared.global [%0], [%1], 16;" :: "r"(s), "l"(g));
}

__global__ __launch_bounds__(256, 2) void gemm_bf16x3(
    const __nv_bfloat16* __restrict__ Ah, const __nv_bfloat16* __restrict__ Al,
    const __nv_bfloat16* __restrict__ Bh, const __nv_bfloat16* __restrict__ Bl,
    const float* __restrict__ bias, float* __restrict__ C, int M, int N, int K)
{
    extern __shared__ char dynsmem[];
    __nv_bfloat16* sm = (__nv_bfloat16*)dynsmem;
    __nv_bfloat16* sAh = sm;               // [2][128][PAD]
    __nv_bfloat16* sAl = sm + 2 * STAGE;
    __nv_bfloat16* sBh = sm + 4 * STAGE;
    __nv_bfloat16* sBl = sm + 6 * STAGE;

    const int m0 = blockIdx.y * 128, n0 = blockIdx.x * 128;
    const int tid = threadIdx.x;
    const int lane = tid & 31, wid = tid >> 5;
    const int g = lane >> 2, t = lane & 3;
    const int mBase = (wid & 3) * 32;
    const int nBase = (wid >> 2) * 64;

    // loader mapping: 2 threads per row, each covers 32B (2 x 16B chunks)
    const int lrow = tid >> 1;
    const int lcol = (tid & 1) * 16;

    const uint32_t sbase = (uint32_t)__cvta_generic_to_shared(sm);
    const uint32_t dAh = sbase + (uint32_t)(lrow * PAD + lcol) * 2;
    const uint32_t dAl = dAh + 2 * STAGE * 2;
    const uint32_t dBh = dAh + 4 * STAGE * 2;
    const uint32_t dBl = dAh + 6 * STAGE * 2;
    const __nv_bfloat16* gAh = Ah + (size_t)(m0 + lrow) * K + lcol;
    const __nv_bfloat16* gAl = Al + (size_t)(m0 + lrow) * K + lcol;
    const __nv_bfloat16* gBh = Bh + (size_t)(n0 + lrow) * K + lcol;
    const __nv_bfloat16* gBl = Bl + (size_t)(n0 + lrow) * K + lcol;

    float acc[2][8][4];
#pragma unroll
    for (int i = 0; i < 2; i++)
#pragma unroll
        for (int j = 0; j < 8; j++)
#pragma unroll
            for (int l = 0; l < 4; l++) acc[i][j][l] = 0.f;

    const int nTiles = K / KT;

    auto issue = [&](int kt, int buf) {
        uint32_t so = (uint32_t)(buf * STAGE * 2);
#pragma unroll
        for (int c = 0; c < 2; c++) {
            cp16(dAh + so + c * 16, gAh + kt + c * 8);
            cp16(dAl + so + c * 16, gAl + kt + c * 8);
            cp16(dBh + so + c * 16, gBh + kt + c * 8);
            cp16(dBl + so + c * 16, gBl + kt + c * 8);
        }
        asm volatile("cp.async.commit_group;");
    };

    issue(0, 0);

    for (int tt = 0; tt < nTiles; tt++) {
        const int buf = tt & 1;
        if (tt + 1 < nTiles) {
            issue((tt + 1) * KT, buf ^ 1);
            asm volatile("cp.async.wait_group 1;");
        } else {
            asm volatile("cp.async.wait_group 0;");
        }
        __syncthreads();

        const __nv_bfloat16* bAh = sAh + buf * STAGE;
        const __nv_bfloat16* bAl = sAl + buf * STAGE;
        const __nv_bfloat16* bBh = sBh + buf * STAGE;
        const __nv_bfloat16* bBl = sBl + buf * STAGE;

#pragma unroll
        for (int k16 = 0; k16 < KT; k16 += 16) {
            uint32_t ah[2][4], al[2][4];
#pragma unroll
            for (int mt = 0; mt < 2; mt++) {
                int r0 = mBase + mt * 16 + g;
                const __nv_bfloat16* ph = bAh + r0 * PAD + k16 + 2 * t;
                const __nv_bfloat16* pl = bAl + r0 * PAD + k16 + 2 * t;
                ah[mt][0] = *(const uint32_t*)ph;
                ah[mt][1] = *(const uint32_t*)(ph + 8 * PAD);
                ah[mt][2] = *(const uint32_t*)(ph + 8);
                ah[mt][3] = *(const uint32_t*)(ph + 8 * PAD + 8);
                al[mt][0] = *(const uint32_t*)pl;
                al[mt][1] = *(const uint32_t*)(pl + 8 * PAD);
                al[mt][2] = *(const uint32_t*)(pl + 8);
                al[mt][3] = *(const uint32_t*)(pl + 8 * PAD + 8);
            }
#pragma unroll
            for (int nt = 0; nt < 8; nt++) {
                int n = nBase + nt * 8 + g;
                const __nv_bfloat16* qh = bBh + n * PAD + k16 + 2 * t;
                const __nv_bfloat16* ql = bBl + n * PAD + k16 + 2 * t;
                uint32_t bh0 = *(const uint32_t*)qh;
                uint32_t bh1 = *(const uint32_t*)(qh + 8);
                uint32_t bl0 = *(const uint32_t*)ql;
                uint32_t bl1 = *(const uint32_t*)(ql + 8);
#pragma unroll
                for (int mt = 0; mt < 2; mt++) {
                    mma16(acc[mt][nt], ah[mt], bh0, bh1);   // hi*hi
                    mma16(acc[mt][nt], ah[mt], bl0, bl1);   // hi*lo
                    mma16(acc[mt][nt], al[mt], bh0, bh1);   // lo*hi
                }
            }
        }
        __syncthreads();
    }

#pragma unroll
    for (int mt = 0; mt < 2; mt++) {
        int r0 = m0 + mBase + mt * 16 + g;
#pragma unroll
        for (int nt = 0; nt < 8; nt++) {
            int c = n0 + nBase + nt * 8 + 2 * t;
            float b0v = bias[c], b1v = bias[c + 1];
            *(float2*)&C[(size_t)r0 * N + c] =
                make_float2(acc[mt][nt][0] + b0v, acc[mt][nt][1] + b1v);
            *(float2*)&C[(size_t)(r0 + 8) * N + c] =
                make_float2(acc[mt][nt][2] + b0v, acc[mt][nt][3] + b1v);
        }
    }
}

// ---------------------------------------------------------------------------
// Flash-style attention with document-block mask + KV-range skipping.
// Writes output pre-split into bf16 hi/lo for the final GEMM.
// ---------------------------------------------------------------------------
__global__ __launch_bounds__(256) void attn_kernel(const float* __restrict__ gq,
    const float* __restrict__ gk, const float* __restrict__ gv,
    const int* __restrict__ doc,
    __nv_bfloat16* __restrict__ aoh, __nv_bfloat16* __restrict__ aol)
{
    extern __shared__ char dynsmem[];
    float* sm = (float*)dynsmem;
    float (*Qs)[HDn + 1] = (float(*)[HDn + 1])sm;
    float (*Ks)[HDn + 1] = (float(*)[HDn + 1])(sm + TQ * (HDn + 1));
    float (*Sc)[TK + 1]  = (float(*)[TK + 1]) (sm + 2 * TQ * (HDn + 1));
    float (*Vs)[HDn]     = (float(*)[HDn])    (sm + 2 * TQ * (HDn + 1) + TQ * (TK + 1));
    __shared__ float m_s[TQ], l_s[TQ], f_s[TQ];
    __shared__ int qdoc[TQ], kdoc[TK], srange[2];

    const int q0 = blockIdx.x * TQ;
    const int h = blockIdx.y, b = blockIdx.z;
    const int tid = threadIdx.x;
    const int tx = tid & 15, ty = tid >> 4;

    if (tid == 0) { srange[0] = Sn; srange[1] = 0; }
    if (tid < TQ) { qdoc[tid] = doc[q0 + tid]; m_s[tid] = -3.4e38f; l_s[tid] = 0.f; }
    __syncthreads();
    const int dlo = qdoc[0], dhi = qdoc[TQ - 1];
    for (int i = tid; i < Sn; i += 256) {
        int di = doc[i];
        if (di == dlo) atomicMin(&srange[0], i);
        if (di == dhi) atomicMax(&srange[1], i);
    }
    const size_t baseq = ((size_t)(b * Sn + q0)) * Dn + h * HDn;
    for (int e = tid; e < TQ * HDn; e += 256) {
        int q = e >> 6, d = e & 63;
        Qs[q][d] = gq[baseq + (size_t)q * Dn + d];
    }
    __syncthreads();
    const int kv_begin = (srange[0] / TK) * TK;
    const int kv_end   = srange[1] + 1;

    float O[4][4] = {};
    for (int k0 = kv_begin; k0 < kv_end; k0 += TK) {
        const size_t basek = ((size_t)(b * Sn + k0)) * Dn + h * HDn;
        for (int e = tid; e < TK * HDn; e += 256) {
            int k = e >> 6, d = e & 63;
            Ks[k][d] = gk[basek + (size_t)k * Dn + d];
            Vs[k][d] = gv[basek + (size_t)k * Dn + d];
        }
        if (tid < TK) kdoc[tid] = doc[k0 + tid];
        __syncthreads();

        float c[4][4] = {};
#pragma unroll
        for (int d = 0; d < HDn; d++) {
            float a[4], bb[4];
#pragma unroll
            for (int i = 0; i < 4; i++) a[i] = Qs[ty * 4 + i][d];
#pragma unroll
            for (int j = 0; j < 4; j++) bb[j] = Ks[tx * 4 + j][d];
#pragma unroll
            for (int i = 0; i < 4; i++)
#pragma unroll
                for (int j = 0; j < 4; j++) c[i][j] += a[i] * bb[j];
        }
#pragma unroll
        for (int i = 0; i < 4; i++) {
            int qd = qdoc[ty * 4 + i];
#pragma unroll
            for (int j = 0; j < 4; j++)
                Sc[ty * 4 + i][tx * 4 + j] =
                    (qd == kdoc[tx * 4 + j]) ? c[i][j] * ATT_SCALE : -1e30f;
        }
        __syncthreads();

        {
            const int r = tid >> 2, p = tid & 3;
            float mx = -3.4e38f;
#pragma unroll
            for (int e = 0; e < 16; e++) mx = fmaxf(mx, Sc[r][p * 16 + e]);
            mx = fmaxf(mx, __shfl_xor_sync(0xffffffffu, mx, 1));
            mx = fmaxf(mx, __shfl_xor_sync(0xffffffffu, mx, 2));
            const float mo = m_s[r];
            const float mn = fmaxf(mo, mx);
            float ps = 0.f;
#pragma unroll
            for (int e = 0; e < 16; e++) {
                float s = Sc[r][p * 16 + e];
                float pe = (s < -1e29f) ? 0.f : __expf(s - mn);
                Sc[r][p * 16 + e] = pe;
                ps += pe;
            }
            ps += __shfl_xor_sync(0xffffffffu, ps, 1);
            ps += __shfl_xor_sync(0xffffffffu, ps, 2);
            if (p == 0) {
                f_s[r] = __expf(mo - mn);
                l_s[r] = l_s[r] * f_s[r] + ps;
                m_s[r] = mn;
            }
        }
        __syncthreads();

#pragma unroll
        for (int i = 0; i < 4; i++) {
            float fi = f_s[ty * 4 + i];
#pragma unroll
            for (int j = 0; j < 4; j++) O[i][j] *= fi;
        }
#pragma unroll
        for (int kk = 0; kk < TK; kk++) {
            float a[4], bb[4];
#pragma unroll
            for (int i = 0; i < 4; i++) a[i] = Sc[ty * 4 + i][kk];
#pragma unroll
            for (int j = 0; j < 4; j++) bb[j] = Vs[kk][tx * 4 + j];
#pragma unroll
            for (int i = 0; i < 4; i++)
#pragma unroll
                for (int j = 0; j < 4; j++) O[i][j] += a[i] * bb[j];
        }
        __syncthreads();
    }

#pragma unroll
    for (int i = 0; i < 4; i++) {
        float inv = 1.f / l_s[ty * 4 + i];
        size_t rb = baseq + (size_t)(ty * 4 + i) * Dn + tx * 4;
#pragma unroll
        for (int j = 0; j < 4; j++) {
            float val = O[i][j] * inv;
            __nv_bfloat16 hv = __float2bfloat16_rn(val);
            aoh[rb + j] = hv;
            aol[rb + j] = __float2bfloat16_rn(val - __bfloat162float(hv));
        }
    }
}

// ---------------------------------------------------------------------------
extern "C" void kernel_launch(void* const* d_in, const int* in_sizes, int n_in,
                              void* d_out, int out_size)
{
    (void)in_sizes; (void)n_in; (void)out_size;
    const float* x  = (const float*)d_in[0];
    const float* wq = (const float*)d_in[1];
    const float* bq = (const float*)d_in[2];
    const float* wk = (const float*)d_in[3];
    const float* bk = (const float*)d_in[4];
    const float* wv = (const float*)d_in[5];
    const float* bv = (const float*)d_in[6];
    const float* wo = (const float*)d_in[7];
    const float* bo = (const float*)d_in[8];
    const int*  doc = (const int*)d_in[9];
    float* out = (float*)d_out;

    float *qp, *kp, *vp;
    __nv_bfloat16 *xh, *xl, *wqh, *wql, *wkh, *wkl, *wvh, *wvl, *woh, *wol, *aoh, *aol;
    cudaGetSymbolAddress((void**)&qp, g_q);
    cudaGetSymbolAddress((void**)&kp, g_k);
    cudaGetSymbolAddress((void**)&vp, g_v);
    cudaGetSymbolAddress((void**)&xh, g_xh);   cudaGetSymbolAddress((void**)&xl, g_xl);
    cudaGetSymbolAddress((void**)&wqh, g_wqh); cudaGetSymbolAddress((void**)&wql, g_wql);
    cudaGetSymbolAddress((void**)&wkh, g_wkh); cudaGetSymbolAddress((void**)&wkl, g_wkl);
    cudaGetSymbolAddress((void**)&wvh, g_wvh); cudaGetSymbolAddress((void**)&wvl, g_wvl);
    cudaGetSymbolAddress((void**)&woh, g_woh); cudaGetSymbolAddress((void**)&wol, g_wol);
    cudaGetSymbolAddress((void**)&aoh, g_aoh); cudaGetSymbolAddress((void**)&aol, g_aol);

    // splits
    const int nX4 = Mn * Dn / 4, nW4 = Dn * Dn / 4;
    split_bf16<<<(nX4 + 255) / 256, 256>>>((const float4*)x,  (__nv_bfloat162*)xh,  (__nv_bfloat162*)xl,  nX4);
    split_bf16<<<(nW4 + 255) / 256, 256>>>((const float4*)wq, (__nv_bfloat162*)wqh, (__nv_bfloat162*)wql, nW4);
    split_bf16<<<(nW4 + 255) / 256, 256>>>((const float4*)wk, (__nv_bfloat162*)wkh, (__nv_bfloat162*)wkl, nW4);
    split_bf16<<<(nW4 + 255) / 256, 256>>>((const float4*)wv, (__nv_bfloat162*)wvh, (__nv_bfloat162*)wvl, nW4);
    split_bf16<<<(nW4 + 255) / 256, 256>>>((const float4*)wo, (__nv_bfloat162*)woh, (__nv_bfloat162*)wol, nW4);

    const int gemm_smem = 8 * STAGE * (int)sizeof(__nv_bfloat16);  // 81920
    cudaFuncSetAttribute(gemm_bf16x3, cudaFuncAttributeMaxDynamicSharedMemorySize, gemm_smem);

    dim3 gg(Dn / 128, Mn / 128);
    gemm_bf16x3<<<gg, 256, gemm_smem>>>(xh, xl, wqh, wql, bq, qp, Mn, Dn, Dn);
    gemm_bf16x3<<<gg, 256, gemm_smem>>>(xh, xl, wkh, wkl, bk, kp, Mn, Dn, Dn);
    gemm_bf16x3<<<gg, 256, gemm_smem>>>(xh, xl, wvh, wvl, bv, vp, Mn, Dn, Dn);

    const int attn_smem = (2 * TQ * (HDn + 1) + TQ * (TK + 1) + TK * HDn) * (int)sizeof(float);
    cudaFuncSetAttribute(attn_kernel, cudaFuncAttributeMaxDynamicSharedMemorySize, attn_smem);
    dim3 ga(Sn / TQ, Hn, Bn);
    attn_kernel<<<ga, 256, attn_smem>>>(qp, kp, vp, doc, aoh, aol);

    gemm_bf16x3<<<gg, 256, gemm_smem>>>(aoh, aol, woh, wol, bo, out, Mn, Dn, Dn);
}

// round 5
// speedup vs baseline: 2.4651x; 1.1213x over previous
#include <cuda_runtime.h>
#include <cuda_bf16.h>
#include <cstdint>

#define Bn 2
#define Sn 2048
#define Dn 1024
#define Hn 16
#define HDn 64
#define Mn (Bn*Sn)
#define ATT_SCALE 0.125f   /* 64^-0.5 */

// bf16 hi/lo splits
static __device__ __nv_bfloat16 g_xh[(size_t)Mn*Dn],  g_xl[(size_t)Mn*Dn];
static __device__ __nv_bfloat16 g_wqh[(size_t)Dn*Dn], g_wql[(size_t)Dn*Dn];
static __device__ __nv_bfloat16 g_wkh[(size_t)Dn*Dn], g_wkl[(size_t)Dn*Dn];
static __device__ __nv_bfloat16 g_wvh[(size_t)Dn*Dn], g_wvl[(size_t)Dn*Dn];
static __device__ __nv_bfloat16 g_woh[(size_t)Dn*Dn], g_wol[(size_t)Dn*Dn];
static __device__ __nv_bfloat16 g_qh[(size_t)Mn*Dn],  g_ql[(size_t)Mn*Dn];
static __device__ __nv_bfloat16 g_kh[(size_t)Mn*Dn],  g_kl[(size_t)Mn*Dn];
static __device__ __nv_bfloat16 g_vh[(size_t)Mn*Dn],  g_vl[(size_t)Mn*Dn];
static __device__ __nv_bfloat16 g_aoh[(size_t)Mn*Dn], g_aol[(size_t)Mn*Dn];

// ---------------------------------------------------------------------------
__global__ __launch_bounds__(256) void split_bf16(const float4* __restrict__ src,
    __nv_bfloat162* __restrict__ hi, __nv_bfloat162* __restrict__ lo, int n4)
{
    int i = blockIdx.x * 256 + threadIdx.x;
    if (i >= n4) return;
    float4 v = src[i];
    __nv_bfloat16 hx = __float2bfloat16_rn(v.x);
    __nv_bfloat16 hy = __float2bfloat16_rn(v.y);
    __nv_bfloat16 hz = __float2bfloat16_rn(v.z);
    __nv_bfloat16 hw = __float2bfloat16_rn(v.w);
    hi[2 * i]     = __nv_bfloat162(hx, hy);
    hi[2 * i + 1] = __nv_bfloat162(hz, hw);
    lo[2 * i]     = __nv_bfloat162(__float2bfloat16_rn(v.x - __bfloat162float(hx)),
                                   __float2bfloat16_rn(v.y - __bfloat162float(hy)));
    lo[2 * i + 1] = __nv_bfloat162(__float2bfloat16_rn(v.z - __bfloat162float(hz)),
                                   __float2bfloat16_rn(v.w - __bfloat162float(hw)));
}

// ---------------------------------------------------------------------------
// helpers
// ---------------------------------------------------------------------------
__device__ __forceinline__ void mma16(float* d, const uint32_t* a,
                                      uint32_t b0, uint32_t b1) {
    asm volatile(
        "mma.sync.aligned.m16n8k16.row.col.f32.bf16.bf16.f32 "
        "{%0,%1,%2,%3},{%4,%5,%6,%7},{%8,%9},{%0,%1,%2,%3};"
        : "+f"(d[0]), "+f"(d[1]), "+f"(d[2]), "+f"(d[3])
        : "r"(a[0]), "r"(a[1]), "r"(a[2]), "r"(a[3]), "r"(b0), "r"(b1));
}

__device__ __forceinline__ void cp16(uint32_t s, const void* g) {
    asm volatile("cp.async.cg.shared.global [%0], [%1], 16;" :: "r"(s), "l"(g));
}

__device__ __forceinline__ void pack_hl(uint32_t& hi, uint32_t& lo, float a, float b) {
    __nv_bfloat162 h = __float22bfloat162_rn(make_float2(a, b));
    float2 hf = __bfloat1622float2(h);
    __nv_bfloat162 l = __float22bfloat162_rn(make_float2(a - hf.x, b - hf.y));
    hi = *(uint32_t*)&h; lo = *(uint32_t*)&l;
}

#define LDSM_X4_T(r0,r1,r2,r3, addr) \
    asm volatile("ldmatrix.sync.aligned.m8n8.x4.trans.shared.b16 {%0,%1,%2,%3}, [%4];" \
        : "=r"(r0), "=r"(r1), "=r"(r2), "=r"(r3) : "r"(addr))

// ---------------------------------------------------------------------------
// 3xBF16 tensor-core GEMM, dual epilogue (fp32 OR hi/lo bf16 split out).
// ---------------------------------------------------------------------------
#define KT 32
#define PAD 40
#define STAGE (128 * PAD)

__global__ __launch_bounds__(256, 2) void gemm_bf16x3(
    const __nv_bfloat16* __restrict__ Ah, const __nv_bfloat16* __restrict__ Al,
    const __nv_bfloat16* __restrict__ Bh, const __nv_bfloat16* __restrict__ Bl,
    const float* __restrict__ bias, float* __restrict__ C,
    __nv_bfloat16* __restrict__ Ch, __nv_bfloat16* __restrict__ Cl,
    int M, int N, int K)
{
    extern __shared__ char dynsmem[];
    __nv_bfloat16* sm = (__nv_bfloat16*)dynsmem;
    __nv_bfloat16* sAh = sm;
    __nv_bfloat16* sAl = sm + 2 * STAGE;
    __nv_bfloat16* sBh = sm + 4 * STAGE;
    __nv_bfloat16* sBl = sm + 6 * STAGE;

    const int m0 = blockIdx.y * 128, n0 = blockIdx.x * 128;
    const int tid = threadIdx.x;
    const int lane = tid & 31, wid = tid >> 5;
    const int g = lane >> 2, t = lane & 3;
    const int mBase = (wid & 3) * 32;
    const int nBase = (wid >> 2) * 64;

    const int lrow = tid >> 1;
    const int lcol = (tid & 1) * 16;

    const uint32_t sbase = (uint32_t)__cvta_generic_to_shared(sm);
    const uint32_t dAh = sbase + (uint32_t)(lrow * PAD + lcol) * 2;
    const uint32_t dAl = dAh + 2 * STAGE * 2;
    const uint32_t dBh = dAh + 4 * STAGE * 2;
    const uint32_t dBl = dAh + 6 * STAGE * 2;
    const __nv_bfloat16* gAh = Ah + (size_t)(m0 + lrow) * K + lcol;
    const __nv_bfloat16* gAl = Al + (size_t)(m0 + lrow) * K + lcol;
    const __nv_bfloat16* gBh = Bh + (size_t)(n0 + lrow) * K + lcol;
    const __nv_bfloat16* gBl = Bl + (size_t)(n0 + lrow) * K + lcol;

    float acc[2][8][4];
#pragma unroll
    for (int i = 0; i < 2; i++)
#pragma unroll
        for (int j = 0; j < 8; j++)
#pragma unroll
            for (int l = 0; l < 4; l++) acc[i][j][l] = 0.f;

    const int nTiles = K / KT;

    auto issue = [&](int kt, int buf) {
        uint32_t so = (uint32_t)(buf * STAGE * 2);
#pragma unroll
        for (int c = 0; c < 2; c++) {
            cp16(dAh + so + c * 16, gAh + kt + c * 8);
            cp16(dAl + so + c * 16, gAl + kt + c * 8);
            cp16(dBh + so + c * 16, gBh + kt + c * 8);
            cp16(dBl + so + c * 16, gBl + kt + c * 8);
        }
        asm volatile("cp.async.commit_group;");
    };

    issue(0, 0);

    for (int tt = 0; tt < nTiles; tt++) {
        const int buf = tt & 1;
        if (tt + 1 < nTiles) {
            issue((tt + 1) * KT, buf ^ 1);
            asm volatile("cp.async.wait_group 1;");
        } else {
            asm volatile("cp.async.wait_group 0;");
        }
        __syncthreads();

        const __nv_bfloat16* bAh = sAh + buf * STAGE;
        const __nv_bfloat16* bAl = sAl + buf * STAGE;
        const __nv_bfloat16* bBh = sBh + buf * STAGE;
        const __nv_bfloat16* bBl = sBl + buf * STAGE;

#pragma unroll
        for (int k16 = 0; k16 < KT; k16 += 16) {
            uint32_t ah[2][4], al[2][4];
#pragma unroll
            for (int mt = 0; mt < 2; mt++) {
                int r0 = mBase + mt * 16 + g;
                const __nv_bfloat16* ph = bAh + r0 * PAD + k16 + 2 * t;
                const __nv_bfloat16* pl = bAl + r0 * PAD + k16 + 2 * t;
                ah[mt][0] = *(const uint32_t*)ph;
                ah[mt][1] = *(const uint32_t*)(ph + 8 * PAD);
                ah[mt][2] = *(const uint32_t*)(ph + 8);
                ah[mt][3] = *(const uint32_t*)(ph + 8 * PAD + 8);
                al[mt][0] = *(const uint32_t*)pl;
                al[mt][1] = *(const uint32_t*)(pl + 8 * PAD);
                al[mt][2] = *(const uint32_t*)(pl + 8);
                al[mt][3] = *(const uint32_t*)(pl + 8 * PAD + 8);
            }
#pragma unroll
            for (int nt = 0; nt < 8; nt++) {
                int n = nBase + nt * 8 + g;
                const __nv_bfloat16* qh = bBh + n * PAD + k16 + 2 * t;
                const __nv_bfloat16* ql = bBl + n * PAD + k16 + 2 * t;
                uint32_t bh0 = *(const uint32_t*)qh;
                uint32_t bh1 = *(const uint32_t*)(qh + 8);
                uint32_t bl0 = *(const uint32_t*)ql;
                uint32_t bl1 = *(const uint32_t*)(ql + 8);
#pragma unroll
                for (int mt = 0; mt < 2; mt++) {
                    mma16(acc[mt][nt], ah[mt], bh0, bh1);
                    mma16(acc[mt][nt], ah[mt], bl0, bl1);
                    mma16(acc[mt][nt], al[mt], bh0, bh1);
                }
            }
        }
        __syncthreads();
    }

#pragma unroll
    for (int mt = 0; mt < 2; mt++) {
        int r0 = m0 + mBase + mt * 16 + g;
#pragma unroll
        for (int nt = 0; nt < 8; nt++) {
            int c = n0 + nBase + nt * 8 + 2 * t;
            float b0v = bias[c], b1v = bias[c + 1];
            float v00 = acc[mt][nt][0] + b0v, v01 = acc[mt][nt][1] + b1v;
            float v10 = acc[mt][nt][2] + b0v, v11 = acc[mt][nt][3] + b1v;
            if (C) {
                *(float2*)&C[(size_t)r0 * N + c] = make_float2(v00, v01);
                *(float2*)&C[(size_t)(r0 + 8) * N + c] = make_float2(v10, v11);
            } else {
                uint32_t h0, l0, h1, l1;
                pack_hl(h0, l0, v00, v01);
                pack_hl(h1, l1, v10, v11);
                *(uint32_t*)&Ch[(size_t)r0 * N + c] = h0;
                *(uint32_t*)&Cl[(size_t)r0 * N + c] = l0;
                *(uint32_t*)&Ch[(size_t)(r0 + 8) * N + c] = h1;
                *(uint32_t*)&Cl[(size_t)(r0 + 8) * N + c] = l1;
            }
        }
    }
}

// ---------------------------------------------------------------------------
// Tensor-core flash attention with doc-block mask + KV range skipping.
// 128 threads = 4 warps; each warp owns 16 q rows x all 64 keys of the tile.
// 3-split bf16 MMAs for both QK^T and PV.
// ---------------------------------------------------------------------------
#define AST 72   /* smem row stride (bf16): 36 words == 4 mod 32 -> conflict-free */

__global__ __launch_bounds__(128) void attn_mma(
    const __nv_bfloat16* __restrict__ gqh, const __nv_bfloat16* __restrict__ gql,
    const __nv_bfloat16* __restrict__ gkh, const __nv_bfloat16* __restrict__ gkl,
    const __nv_bfloat16* __restrict__ gvh, const __nv_bfloat16* __restrict__ gvl,
    const int* __restrict__ doc,
    __nv_bfloat16* __restrict__ aoh, __nv_bfloat16* __restrict__ aol)
{
    extern __shared__ char dynsmem[];
    __nv_bfloat16* sKh = (__nv_bfloat16*)dynsmem;   // [64][AST]
    __nv_bfloat16* sKl = sKh + 64 * AST;
    __nv_bfloat16* sVh = sKl + 64 * AST;
    __nv_bfloat16* sVl = sVh + 64 * AST;
    __shared__ int qdoc[64], kdoc[64], srange[2];

    const int q0 = blockIdx.x * 64;
    const int h = blockIdx.y, b = blockIdx.z;
    const int tid = threadIdx.x;
    const int lane = tid & 31, w = tid >> 5;
    const int g = lane >> 2, t = lane & 3;
    const int wrow = w * 16;

    if (tid == 0) { srange[0] = Sn; srange[1] = 0; }
    if (tid < 64) qdoc[tid] = doc[q0 + tid];
    __syncthreads();
    const int dlo = qdoc[0], dhi = qdoc[63];
    for (int i = tid; i < Sn; i += 128) {
        int di = doc[i];
        if (di == dlo) atomicMin(&srange[0], i);
        if (di == dhi) atomicMax(&srange[1], i);
    }

    // stage Q (hi->sKh, lo->sKl), then lift fragments to registers
    const size_t rowbase = (size_t)(b * Sn + q0) * Dn + h * HDn;
    for (int v = tid; v < 512; v += 128) {
        int r = v >> 3, cg = (v & 7) * 8;
        *(uint4*)&sKh[r * AST + cg] = *(const uint4*)&gqh[rowbase + (size_t)r * Dn + cg];
        *(uint4*)&sKl[r * AST + cg] = *(const uint4*)&gql[rowbase + (size_t)r * Dn + cg];
    }
    __syncthreads();

    uint32_t qfh[4][4], qfl[4][4];
#pragma unroll
    for (int ks = 0; ks < 4; ks++) {
        int r0 = (wrow + g) * AST, r8 = (wrow + g + 8) * AST, c = ks * 16 + 2 * t;
        qfh[ks][0] = *(uint32_t*)&sKh[r0 + c];
        qfh[ks][1] = *(uint32_t*)&sKh[r8 + c];
        qfh[ks][2] = *(uint32_t*)&sKh[r0 + c + 8];
        qfh[ks][3] = *(uint32_t*)&sKh[r8 + c + 8];
        qfl[ks][0] = *(uint32_t*)&sKl[r0 + c];
        qfl[ks][1] = *(uint32_t*)&sKl[r8 + c];
        qfl[ks][2] = *(uint32_t*)&sKl[r0 + c + 8];
        qfl[ks][3] = *(uint32_t*)&sKl[r8 + c + 8];
    }
    __syncthreads();   // also makes srange visible

    const int qd0 = qdoc[wrow + g], qd8 = qdoc[wrow + g + 8];
    const int kv_begin = (srange[0] / 64) * 64;
    const int kv_end   = srange[1] + 1;

    const uint32_t svh = (uint32_t)__cvta_generic_to_shared(sVh);
    const uint32_t svl = (uint32_t)__cvta_generic_to_shared(sVl);
    const uint32_t lmoff = (uint32_t)(((lane & 15) * AST + ((lane >> 4) << 3)) * 2);

    float o[8][4];
#pragma unroll
    for (int i = 0; i < 8; i++)
#pragma unroll
        for (int j = 0; j < 4; j++) o[i][j] = 0.f;
    float m0 = -1e30f, m8 = -1e30f, l0 = 0.f, l8 = 0.f;

    for (int k0 = kv_begin; k0 < kv_end; k0 += 64) {
        const size_t kb = (size_t)(b * Sn + k0) * Dn + h * HDn;
        for (int v = tid; v < 512; v += 128) {
            int r = v >> 3, cg = (v & 7) * 8;
            size_t src = kb + (size_t)r * Dn + cg;
            int dst = r * AST + cg;
            *(uint4*)&sKh[dst] = *(const uint4*)&gkh[src];
            *(uint4*)&sKl[dst] = *(const uint4*)&gkl[src];
            *(uint4*)&sVh[dst] = *(const uint4*)&gvh[src];
            *(uint4*)&sVl[dst] = *(const uint4*)&gvl[src];
        }
        if (tid < 64) kdoc[tid] = doc[k0 + tid];
        __syncthreads();

        // S = Q K^T (3-split)
        float s[8][4];
#pragma unroll
        for (int i = 0; i < 8; i++)
#pragma unroll
            for (int j = 0; j < 4; j++) s[i][j] = 0.f;
#pragma unroll
        for (int ks = 0; ks < 4; ks++) {
#pragma unroll
            for (int nt = 0; nt < 8; nt++) {
                int rb = (nt * 8 + g) * AST + ks * 16 + 2 * t;
                uint32_t bh0 = *(uint32_t*)&sKh[rb];
                uint32_t bh1 = *(uint32_t*)&sKh[rb + 8];
                uint32_t bl0 = *(uint32_t*)&sKl[rb];
                uint32_t bl1 = *(uint32_t*)&sKl[rb + 8];
                mma16(s[nt], qfh[ks], bh0, bh1);
                mma16(s[nt], qfh[ks], bl0, bl1);
                mma16(s[nt], qfl[ks], bh0, bh1);
            }
        }

        // mask + scale + online softmax (rows g / g+8, quad-reduced)
        float mx0 = -1e30f, mx8 = -1e30f;
#pragma unroll
        for (int nt = 0; nt < 8; nt++) {
            int kd0 = kdoc[nt * 8 + 2 * t], kd1 = kdoc[nt * 8 + 2 * t + 1];
            s[nt][0] = (qd0 == kd0) ? s[nt][0] * ATT_SCALE : -1e30f;
            s[nt][1] = (qd0 == kd1) ? s[nt][1] * ATT_SCALE : -1e30f;
            s[nt][2] = (qd8 == kd0) ? s[nt][2] * ATT_SCALE : -1e30f;
            s[nt][3] = (qd8 == kd1) ? s[nt][3] * ATT_SCALE : -1e30f;
            mx0 = fmaxf(mx0, fmaxf(s[nt][0], s[nt][1]));
            mx8 = fmaxf(mx8, fmaxf(s[nt][2], s[nt][3]));
        }
        mx0 = fmaxf(mx0, __shfl_xor_sync(0xffffffffu, mx0, 1));
        mx0 = fmaxf(mx0, __shfl_xor_sync(0xffffffffu, mx0, 2));
        mx8 = fmaxf(mx8, __shfl_xor_sync(0xffffffffu, mx8, 1));
        mx8 = fmaxf(mx8, __shfl_xor_sync(0xffffffffu, mx8, 2));
        const float mn0 = fmaxf(m0, mx0), mn8 = fmaxf(m8, mx8);
        const float f0 = __expf(m0 - mn0), f8 = __expf(m8 - mn8);
        float sum0 = 0.f, sum8 = 0.f;
#pragma unroll
        for (int nt = 0; nt < 8; nt++) {
            s[nt][0] = (s[nt][0] > -1e29f) ? __expf(s[nt][0] - mn0) : 0.f;
            s[nt][1] = (s[nt][1] > -1e29f) ? __expf(s[nt][1] - mn0) : 0.f;
            s[nt][2] = (s[nt][2] > -1e29f) ? __expf(s[nt][2] - mn8) : 0.f;
            s[nt][3] = (s[nt][3] > -1e29f) ? __expf(s[nt][3] - mn8) : 0.f;
            sum0 += s[nt][0] + s[nt][1];
            sum8 += s[nt][2] + s[nt][3];
        }
        sum0 += __shfl_xor_sync(0xffffffffu, sum0, 1);
        sum0 += __shfl_xor_sync(0xffffffffu, sum0, 2);
        sum8 += __shfl_xor_sync(0xffffffffu, sum8, 1);
        sum8 += __shfl_xor_sync(0xffffffffu, sum8, 2);
        l0 = l0 * f0 + sum0;  l8 = l8 * f8 + sum8;
        m0 = mn0;             m8 = mn8;
#pragma unroll
        for (int nt = 0; nt < 8; nt++) {
            o[nt][0] *= f0; o[nt][1] *= f0;
            o[nt][2] *= f8; o[nt][3] *= f8;
        }

        // O += P V (3-split); P acc-layout == A-fragment layout (no shuffles)
#pragma unroll
        for (int ks = 0; ks < 4; ks++) {
            uint32_t pah[4], pal[4];
            pack_hl(pah[0], pal[0], s[2 * ks][0],     s[2 * ks][1]);
            pack_hl(pah[1], pal[1], s[2 * ks][2],     s[2 * ks][3]);
            pack_hl(pah[2], pal[2], s[2 * ks + 1][0], s[2 * ks + 1][1]);
            pack_hl(pah[3], pal[3], s[2 * ks + 1][2], s[2 * ks + 1][3]);
            uint32_t rowoff = (uint32_t)(ks * 16 * AST * 2) + lmoff;
#pragma unroll
            for (int dg = 0; dg < 4; dg++) {
                uint32_t addr = rowoff + (uint32_t)(dg * 16 * 2);
                uint32_t h0, h1, h2, h3, L0, L1, L2, L3;
                LDSM_X4_T(h0, h1, h2, h3, svh + addr);
                LDSM_X4_T(L0, L1, L2, L3, svl + addr);
                mma16(o[2 * dg],     pah, h0, h1);
                mma16(o[2 * dg],     pal, h0, h1);
                mma16(o[2 * dg],     pah, L0, L1);
                mma16(o[2 * dg + 1], pah, h2, h3);
                mma16(o[2 * dg + 1], pal, h2, h3);
                mma16(o[2 * dg + 1], pah, L2, L3);
            }
        }
        __syncthreads();
    }

    const float inv0 = 1.f / l0, inv8 = 1.f / l8;
    const size_t ob0 = rowbase + (size_t)(wrow + g) * Dn;
    const size_t ob8 = rowbase + (size_t)(wrow + g + 8) * Dn;
#pragma unroll
    for (int nt = 0; nt < 8; nt++) {
        int c = nt * 8 + 2 * t;
        uint32_t h0, l0r, h1, l1r;
        pack_hl(h0, l0r, o[nt][0] * inv0, o[nt][1] * inv0);
        pack_hl(h1, l1r, o[nt][2] * inv8, o[nt][3] * inv8);
        *(uint32_t*)&aoh[ob0 + c] = h0;
        *(uint32_t*)&aol[ob0 + c] = l0r;
        *(uint32_t*)&aoh[ob8 + c] = h1;
        *(uint32_t*)&aol[ob8 + c] = l1r;
    }
}

// ---------------------------------------------------------------------------
extern "C" void kernel_launch(void* const* d_in, const int* in_sizes, int n_in,
                              void* d_out, int out_size)
{
    (void)in_sizes; (void)n_in; (void)out_size;
    const float* x  = (const float*)d_in[0];
    const float* wq = (const float*)d_in[1];
    const float* bq = (const float*)d_in[2];
    const float* wk = (const float*)d_in[3];
    const float* bk = (const float*)d_in[4];
    const float* wv = (const float*)d_in[5];
    const float* bv = (const float*)d_in[6];
    const float* wo = (const float*)d_in[7];
    const float* bo = (const float*)d_in[8];
    const int*  doc = (const int*)d_in[9];
    float* out = (float*)d_out;

    __nv_bfloat16 *xh, *xl, *wqh, *wql, *wkh, *wkl, *wvh, *wvl, *woh, *wol;
    __nv_bfloat16 *qh, *ql, *kh, *kl, *vh, *vl, *aoh, *aol;
    cudaGetSymbolAddress((void**)&xh, g_xh);   cudaGetSymbolAddress((void**)&xl, g_xl);
    cudaGetSymbolAddress((void**)&wqh, g_wqh); cudaGetSymbolAddress((void**)&wql, g_wql);
    cudaGetSymbolAddress((void**)&wkh, g_wkh); cudaGetSymbolAddress((void**)&wkl, g_wkl);
    cudaGetSymbolAddress((void**)&wvh, g_wvh); cudaGetSymbolAddress((void**)&wvl, g_wvl);
    cudaGetSymbolAddress((void**)&woh, g_woh); cudaGetSymbolAddress((void**)&wol, g_wol);
    cudaGetSymbolAddress((void**)&qh, g_qh);   cudaGetSymbolAddress((void**)&ql, g_ql);
    cudaGetSymbolAddress((void**)&kh, g_kh);   cudaGetSymbolAddress((void**)&kl, g_kl);
    cudaGetSymbolAddress((void**)&vh, g_vh);   cudaGetSymbolAddress((void**)&vl, g_vl);
    cudaGetSymbolAddress((void**)&aoh, g_aoh); cudaGetSymbolAddress((void**)&aol, g_aol);

    const int nX4 = Mn * Dn / 4, nW4 = Dn * Dn / 4;
    split_bf16<<<(nX4 + 255) / 256, 256>>>((const float4*)x,  (__nv_bfloat162*)xh,  (__nv_bfloat162*)xl,  nX4);
    split_bf16<<<(nW4 + 255) / 256, 256>>>((const float4*)wq, (__nv_bfloat162*)wqh, (__nv_bfloat162*)wql, nW4);
    split_bf16<<<(nW4 + 255) / 256, 256>>>((const float4*)wk, (__nv_bfloat162*)wkh, (__nv_bfloat162*)wkl, nW4);
    split_bf16<<<(nW4 + 255) / 256, 256>>>((const float4*)wv, (__nv_bfloat162*)wvh, (__nv_bfloat162*)wvl, nW4);
    split_bf16<<<(nW4 + 255) / 256, 256>>>((const float4*)wo, (__nv_bfloat162*)woh, (__nv_bfloat162*)wol, nW4);

    const int gemm_smem = 8 * STAGE * (int)sizeof(__nv_bfloat16);  // 81920
    cudaFuncSetAttribute(gemm_bf16x3, cudaFuncAttributeMaxDynamicSharedMemorySize, gemm_smem);

    dim3 gg(Dn / 128, Mn / 128);
    gemm_bf16x3<<<gg, 256, gemm_smem>>>(xh, xl, wqh, wql, bq, nullptr, qh, ql, Mn, Dn, Dn);
    gemm_bf16x3<<<gg, 256, gemm_smem>>>(xh, xl, wkh, wkl, bk, nullptr, kh, kl, Mn, Dn, Dn);
    gemm_bf16x3<<<gg, 256, gemm_smem>>>(xh, xl, wvh, wvl, bv, nullptr, vh, vl, Mn, Dn, Dn);

    const int attn_smem = 4 * 64 * AST * (int)sizeof(__nv_bfloat16);  // 36864
    cudaFuncSetAttribute(attn_mma, cudaFuncAttributeMaxDynamicSharedMemorySize, attn_smem);
    dim3 ga(Sn / 64, Hn, Bn);
    attn_mma<<<ga, 128, attn_smem>>>(qh, ql, kh, kl, vh, vl, doc, aoh, aol);

    gemm_bf16x3<<<gg, 256, gemm_smem>>>(aoh, aol, woh, wol, bo, out, nullptr, nullptr, Mn, Dn, Dn);
}

// round 7
// speedup vs baseline: 2.7458x; 1.1139x over previous
#include <cuda_runtime.h>
#include <cuda_bf16.h>
#include <cstdint>

#define Bn 2
#define Sn 2048
#define Dn 1024
#define Hn 16
#define HDn 64
#define Mn (Bn*Sn)
#define ATT_SCALE 0.125f   /* 64^-0.5 */

// bf16 hi/lo splits
static __device__ __nv_bfloat16 g_xh[(size_t)Mn*Dn],  g_xl[(size_t)Mn*Dn];
static __device__ __nv_bfloat16 g_wqh[(size_t)Dn*Dn], g_wql[(size_t)Dn*Dn];
static __device__ __nv_bfloat16 g_wkh[(size_t)Dn*Dn], g_wkl[(size_t)Dn*Dn];
static __device__ __nv_bfloat16 g_wvh[(size_t)Dn*Dn], g_wvl[(size_t)Dn*Dn];
static __device__ __nv_bfloat16 g_woh[(size_t)Dn*Dn], g_wol[(size_t)Dn*Dn];
static __device__ __nv_bfloat16 g_qh[(size_t)Mn*Dn],  g_ql[(size_t)Mn*Dn];
static __device__ __nv_bfloat16 g_kh[(size_t)Mn*Dn],  g_kl[(size_t)Mn*Dn];
static __device__ __nv_bfloat16 g_vh[(size_t)Mn*Dn],  g_vl[(size_t)Mn*Dn];
static __device__ __nv_bfloat16 g_aoh[(size_t)Mn*Dn], g_aol[(size_t)Mn*Dn];

// ---------------------------------------------------------------------------
// splits
// ---------------------------------------------------------------------------
__device__ __forceinline__ void split1(float4 v, __nv_bfloat162* hi,
                                       __nv_bfloat162* lo, int i) {
    __nv_bfloat16 hx = __float2bfloat16_rn(v.x);
    __nv_bfloat16 hy = __float2bfloat16_rn(v.y);
    __nv_bfloat16 hz = __float2bfloat16_rn(v.z);
    __nv_bfloat16 hw = __float2bfloat16_rn(v.w);
    hi[2 * i]     = __nv_bfloat162(hx, hy);
    hi[2 * i + 1] = __nv_bfloat162(hz, hw);
    lo[2 * i]     = __nv_bfloat162(__float2bfloat16_rn(v.x - __bfloat162float(hx)),
                                   __float2bfloat16_rn(v.y - __bfloat162float(hy)));
    lo[2 * i + 1] = __nv_bfloat162(__float2bfloat16_rn(v.z - __bfloat162float(hz)),
                                   __float2bfloat16_rn(v.w - __bfloat162float(hw)));
}

__global__ __launch_bounds__(256) void split_bf16(const float4* __restrict__ src,
    __nv_bfloat162* __restrict__ hi, __nv_bfloat162* __restrict__ lo, int n4)
{
    int i = blockIdx.x * 256 + threadIdx.x;
    if (i >= n4) return;
    split1(src[i], hi, lo, i);
}

// merged split for the 4 weight matrices
__global__ __launch_bounds__(256) void split_w4(
    const float4* __restrict__ s0, const float4* __restrict__ s1,
    const float4* __restrict__ s2, const float4* __restrict__ s3,
    __nv_bfloat162* __restrict__ h0, __nv_bfloat162* __restrict__ l0,
    __nv_bfloat162* __restrict__ h1, __nv_bfloat162* __restrict__ l1,
    __nv_bfloat162* __restrict__ h2, __nv_bfloat162* __restrict__ l2,
    __nv_bfloat162* __restrict__ h3, __nv_bfloat162* __restrict__ l3, int n4)
{
    int i = blockIdx.x * 256 + threadIdx.x;
    if (i >= n4) return;
    int w = blockIdx.y;
    const float4* s = (w == 0) ? s0 : (w == 1) ? s1 : (w == 2) ? s2 : s3;
    __nv_bfloat162* h = (w == 0) ? h0 : (w == 1) ? h1 : (w == 2) ? h2 : h3;
    __nv_bfloat162* l = (w == 0) ? l0 : (w == 1) ? l1 : (w == 2) ? l2 : l3;
    split1(s[i], h, l, i);
}

// ---------------------------------------------------------------------------
// helpers
// ---------------------------------------------------------------------------
__device__ __forceinline__ uint32_t s2u(const void* p) {
    return (uint32_t)__cvta_generic_to_shared(p);
}

__device__ __forceinline__ void mma16(float* d, const uint32_t* a,
                                      uint32_t b0, uint32_t b1) {
    asm volatile(
        "mma.sync.aligned.m16n8k16.row.col.f32.bf16.bf16.f32 "
        "{%0,%1,%2,%3},{%4,%5,%6,%7},{%8,%9},{%0,%1,%2,%3};"
        : "+f"(d[0]), "+f"(d[1]), "+f"(d[2]), "+f"(d[3])
        : "r"(a[0]), "r"(a[1]), "r"(a[2]), "r"(a[3]), "r"(b0), "r"(b1));
}

__device__ __forceinline__ void cp16(uint32_t s, const void* g) {
    asm volatile("cp.async.cg.shared.global [%0], [%1], 16;" :: "r"(s), "l"(g));
}

__device__ __forceinline__ void pack_hl(uint32_t& hi, uint32_t& lo, float a, float b) {
    __nv_bfloat162 h = __float22bfloat162_rn(make_float2(a, b));
    float2 hf = __bfloat1622float2(h);
    __nv_bfloat162 l = __float22bfloat162_rn(make_float2(a - hf.x, b - hf.y));
    hi = *(uint32_t*)&h; lo = *(uint32_t*)&l;
}

#define LDSM_X4(r0,r1,r2,r3, addr) \
    asm volatile("ldmatrix.sync.aligned.m8n8.x4.shared.b16 {%0,%1,%2,%3}, [%4];" \
        : "=r"(r0), "=r"(r1), "=r"(r2), "=r"(r3) : "r"(addr))

#define LDSM_X4_T(r0,r1,r2,r3, addr) \
    asm volatile("ldmatrix.sync.aligned.m8n8.x4.trans.shared.b16 {%0,%1,%2,%3}, [%4];" \
        : "=r"(r0), "=r"(r1), "=r"(r2), "=r"(r3) : "r"(addr))

// ---------------------------------------------------------------------------
// 3xBF16 tensor-core GEMM (unified QKV / O). Block 128x128, KT=32, cp.async
// double-buffered, ldmatrix fragment loads. grid.x = 8*numW; wsel = bx>>3.
// ---------------------------------------------------------------------------
#define KT 32
#define PAD 40
#define STAGE (128 * PAD)

__global__ __launch_bounds__(256, 2) void gemm_uni(
    const __nv_bfloat16* __restrict__ Ah, const __nv_bfloat16* __restrict__ Al,
    const __nv_bfloat16* __restrict__ Bh0, const __nv_bfloat16* __restrict__ Bl0,
    const __nv_bfloat16* __restrict__ Bh1, const __nv_bfloat16* __restrict__ Bl1,
    const __nv_bfloat16* __restrict__ Bh2, const __nv_bfloat16* __restrict__ Bl2,
    const float* __restrict__ bias0, const float* __restrict__ bias1,
    const float* __restrict__ bias2,
    float* __restrict__ C,
    __nv_bfloat16* __restrict__ Ch0, __nv_bfloat16* __restrict__ Cl0,
    __nv_bfloat16* __restrict__ Ch1, __nv_bfloat16* __restrict__ Cl1,
    __nv_bfloat16* __restrict__ Ch2, __nv_bfloat16* __restrict__ Cl2,
    int M, int N, int K)
{
    extern __shared__ char dynsmem[];
    __nv_bfloat16* sm = (__nv_bfloat16*)dynsmem;
    __nv_bfloat16* sAh = sm;
    __nv_bfloat16* sAl = sm + 2 * STAGE;
    __nv_bfloat16* sBh = sm + 4 * STAGE;
    __nv_bfloat16* sBl = sm + 6 * STAGE;

    const int wsel = blockIdx.x >> 3;
    const __nv_bfloat16* Bh = (wsel == 0) ? Bh0 : (wsel == 1) ? Bh1 : Bh2;
    const __nv_bfloat16* Bl = (wsel == 0) ? Bl0 : (wsel == 1) ? Bl1 : Bl2;
    const float* bias = (wsel == 0) ? bias0 : (wsel == 1) ? bias1 : bias2;
    __nv_bfloat16* Ch = (wsel == 0) ? Ch0 : (wsel == 1) ? Ch1 : Ch2;
    __nv_bfloat16* Cl = (wsel == 0) ? Cl0 : (wsel == 1) ? Cl1 : Cl2;

    const int m0 = blockIdx.y * 128, n0 = (blockIdx.x & 7) * 128;
    const int tid = threadIdx.x;
    const int lane = tid & 31, wid = tid >> 5;
    const int g = lane >> 2, t = lane & 3;
    const int mBase = (wid & 3) * 32;
    const int nBase = (wid >> 2) * 64;

    const int lrow = tid >> 1;
    const int lcol = (tid & 1) * 16;

    const uint32_t sbase = s2u(sm);
    const uint32_t dAh = sbase + (uint32_t)(lrow * PAD + lcol) * 2;
    const uint32_t dAl = dAh + 2 * STAGE * 2;
    const uint32_t dBh = dAh + 4 * STAGE * 2;
    const uint32_t dBl = dAh + 6 * STAGE * 2;
    const __nv_bfloat16* gAh = Ah + (size_t)(m0 + lrow) * K + lcol;
    const __nv_bfloat16* gAl = Al + (size_t)(m0 + lrow) * K + lcol;
    const __nv_bfloat16* gBh = Bh + (size_t)(n0 + lrow) * K + lcol;
    const __nv_bfloat16* gBl = Bl + (size_t)(n0 + lrow) * K + lcol;

    // ldmatrix lane address components
    const int arow = lane & 15;                      // A: row within 16
    const int acol = (lane >> 4) << 3;               // A: k half
    const int brow = (lane & 7) + ((lane >> 4) << 3);// B: row within 16 (pair)
    const int bcol = ((lane >> 3) & 1) << 3;         // B: k half

    float acc[2][8][4];
#pragma unroll
    for (int i = 0; i < 2; i++)
#pragma unroll
        for (int j = 0; j < 8; j++)
#pragma unroll
            for (int l = 0; l < 4; l++) acc[i][j][l] = 0.f;

    const int nTiles = K / KT;

    auto issue = [&](int kt, int buf) {
        uint32_t so = (uint32_t)(buf * STAGE * 2);
#pragma unroll
        for (int c = 0; c < 2; c++) {
            cp16(dAh + so + c * 16, gAh + kt + c * 8);
            cp16(dAl + so + c * 16, gAl + kt + c * 8);
            cp16(dBh + so + c * 16, gBh + kt + c * 8);
            cp16(dBl + so + c * 16, gBl + kt + c * 8);
        }
        asm volatile("cp.async.commit_group;");
    };

    issue(0, 0);

    for (int tt = 0; tt < nTiles; tt++) {
        const int buf = tt & 1;
        if (tt + 1 < nTiles) {
            issue((tt + 1) * KT, buf ^ 1);
            asm volatile("cp.async.wait_group 1;");
        } else {
            asm volatile("cp.async.wait_group 0;");
        }
        __syncthreads();

        const uint32_t uAh = s2u(sAh + buf * STAGE);
        const uint32_t uAl = s2u(sAl + buf * STAGE);
        const uint32_t uBh = s2u(sBh + buf * STAGE);
        const uint32_t uBl = s2u(sBl + buf * STAGE);

#pragma unroll
        for (int k16 = 0; k16 < KT; k16 += 16) {
            uint32_t ah[2][4], al[2][4];
#pragma unroll
            for (int mt = 0; mt < 2; mt++) {
                uint32_t aoff = (uint32_t)(((mBase + mt * 16 + arow) * PAD + k16 + acol) * 2);
                LDSM_X4(ah[mt][0], ah[mt][1], ah[mt][2], ah[mt][3], uAh + aoff);
                LDSM_X4(al[mt][0], al[mt][1], al[mt][2], al[mt][3], uAl + aoff);
            }
#pragma unroll
            for (int ntp = 0; ntp < 4; ntp++) {
                uint32_t boff = (uint32_t)(((nBase + ntp * 16 + brow) * PAD + k16 + bcol) * 2);
                uint32_t bh0, bh1, bh2, bh3, bl0, bl1, bl2, bl3;
                LDSM_X4(bh0, bh1, bh2, bh3, uBh + boff);
                LDSM_X4(bl0, bl1, bl2, bl3, uBl + boff);
#pragma unroll
                for (int mt = 0; mt < 2; mt++) {
                    mma16(acc[mt][2 * ntp],     ah[mt], bh0, bh1);
                    mma16(acc[mt][2 * ntp],     ah[mt], bl0, bl1);
                    mma16(acc[mt][2 * ntp],     al[mt], bh0, bh1);
                    mma16(acc[mt][2 * ntp + 1], ah[mt], bh2, bh3);
                    mma16(acc[mt][2 * ntp + 1], ah[mt], bl2, bl3);
                    mma16(acc[mt][2 * ntp + 1], al[mt], bh2, bh3);
                }
            }
        }
        __syncthreads();
    }

#pragma unroll
    for (int mt = 0; mt < 2; mt++) {
        int r0 = m0 + mBase + mt * 16 + g;
#pragma unroll
        for (int nt = 0; nt < 8; nt++) {
            int c = n0 + nBase + nt * 8 + 2 * t;
            float b0v = bias[c], b1v = bias[c + 1];
            float v00 = acc[mt][nt][0] + b0v, v01 = acc[mt][nt][1] + b1v;
            float v10 = acc[mt][nt][2] + b0v, v11 = acc[mt][nt][3] + b1v;
            if (C) {
                *(float2*)&C[(size_t)r0 * N + c] = make_float2(v00, v01);
                *(float2*)&C[(size_t)(r0 + 8) * N + c] = make_float2(v10, v11);
            } else {
                uint32_t h0, l0, h1, l1;
                pack_hl(h0, l0, v00, v01);
                pack_hl(h1, l1, v10, v11);
                *(uint32_t*)&Ch[(size_t)r0 * N + c] = h0;
                *(uint32_t*)&Cl[(size_t)r0 * N + c] = l0;
                *(uint32_t*)&Ch[(size_t)(r0 + 8) * N + c] = h1;
                *(uint32_t*)&Cl[(size_t)(r0 + 8) * N + c] = l1;
            }
        }
    }
}

// ---------------------------------------------------------------------------
// Tensor-core flash attention with doc-block mask + KV range skipping.
// 128 threads = 4 warps; warp owns 16 q rows. ldmatrix K/V fragment loads.
// ---------------------------------------------------------------------------
#define AST 72

__global__ __launch_bounds__(128, 3) void attn_mma(
    const __nv_bfloat16* __restrict__ gqh, const __nv_bfloat16* __restrict__ gql,
    const __nv_bfloat16* __restrict__ gkh, const __nv_bfloat16* __restrict__ gkl,
    const __nv_bfloat16* __restrict__ gvh, const __nv_bfloat16* __restrict__ gvl,
    const int* __restrict__ doc,
    __nv_bfloat16* __restrict__ aoh, __nv_bfloat16* __restrict__ aol)
{
    extern __shared__ char dynsmem[];
    __nv_bfloat16* sKh = (__nv_bfloat16*)dynsmem;
    __nv_bfloat16* sKl = sKh + 64 * AST;
    __nv_bfloat16* sVh = sKl + 64 * AST;
    __nv_bfloat16* sVl = sVh + 64 * AST;
    __shared__ int qdoc[64], kdoc[64], srange[2];

    const int q0 = blockIdx.x * 64;
    const int h = blockIdx.y, b = blockIdx.z;
    const int tid = threadIdx.x;
    const int lane = tid & 31, w = tid >> 5;
    const int g = lane >> 2, t = lane & 3;
    const int wrow = w * 16;

    if (tid == 0) { srange[0] = Sn; srange[1] = 0; }
    if (tid < 64) qdoc[tid] = doc[q0 + tid];
    __syncthreads();
    const int dlo = qdoc[0], dhi = qdoc[63];
    for (int i = tid; i < Sn; i += 128) {
        int di = doc[i];
        if (di == dlo) atomicMin(&srange[0], i);
        if (di == dhi) atomicMax(&srange[1], i);
    }

    // Q fragments directly from global (once per block)
    const size_t rowbase = (size_t)(b * Sn + q0) * Dn + h * HDn;
    uint32_t qfh[4][4], qfl[4][4];
    {
        const size_t r0 = rowbase + (size_t)(wrow + g) * Dn + 2 * t;
        const size_t r8 = rowbase + (size_t)(wrow + g + 8) * Dn + 2 * t;
#pragma unroll
        for (int ks = 0; ks < 4; ks++) {
            int c = ks * 16;
            qfh[ks][0] = *(const uint32_t*)&gqh[r0 + c];
            qfh[ks][1] = *(const uint32_t*)&gqh[r8 + c];
            qfh[ks][2] = *(const uint32_t*)&gqh[r0 + c + 8];
            qfh[ks][3] = *(const uint32_t*)&gqh[r8 + c + 8];
            qfl[ks][0] = *(const uint32_t*)&gql[r0 + c];
            qfl[ks][1] = *(const uint32_t*)&gql[r8 + c];
            qfl[ks][2] = *(const uint32_t*)&gql[r0 + c + 8];
            qfl[ks][3] = *(const uint32_t*)&gql[r8 + c + 8];
        }
    }
    __syncthreads();   // srange ready

    const int qd0 = qdoc[wrow + g], qd8 = qdoc[wrow + g + 8];
    const int kv_begin = (srange[0] / 64) * 64;
    const int kv_end   = srange[1] + 1;

    const uint32_t ukh = s2u(sKh), ukl = s2u(sKl);
    const uint32_t uvh = s2u(sVh), uvl = s2u(sVl);
    // K ldmatrix (non-trans, B-pair pattern)
    const int brow = (lane & 7) + ((lane >> 4) << 3);
    const int bcol = ((lane >> 3) & 1) << 3;
    // V ldmatrix (trans)
    const uint32_t lmoff = (uint32_t)(((lane & 15) * AST + ((lane >> 4) << 3)) * 2);

    float o[8][4];
#pragma unroll
    for (int i = 0; i < 8; i++)
#pragma unroll
        for (int j = 0; j < 4; j++) o[i][j] = 0.f;
    float m0 = -1e30f, m8 = -1e30f, l0 = 0.f, l8 = 0.f;

    for (int k0 = kv_begin; k0 < kv_end; k0 += 64) {
        const size_t kb = (size_t)(b * Sn + k0) * Dn + h * HDn;
        for (int v = tid; v < 512; v += 128) {
            int r = v >> 3, cg = (v & 7) * 8;
            size_t src = kb + (size_t)r * Dn + cg;
            int dst = r * AST + cg;
            *(uint4*)&sKh[dst] = *(const uint4*)&gkh[src];
            *(uint4*)&sKl[dst] = *(const uint4*)&gkl[src];
            *(uint4*)&sVh[dst] = *(const uint4*)&gvh[src];
            *(uint4*)&sVl[dst] = *(const uint4*)&gvl[src];
        }
        if (tid < 64) kdoc[tid] = doc[k0 + tid];
        __syncthreads();

        // S = Q K^T (3-split), K frags via ldmatrix.x4 (2 n-tiles per op)
        float s[8][4];
#pragma unroll
        for (int i = 0; i < 8; i++)
#pragma unroll
            for (int j = 0; j < 4; j++) s[i][j] = 0.f;
#pragma unroll
        for (int ks = 0; ks < 4; ks++) {
#pragma unroll
            for (int ntp = 0; ntp < 4; ntp++) {
                uint32_t koff = (uint32_t)(((ntp * 16 + brow) * AST + ks * 16 + bcol) * 2);
                uint32_t bh0, bh1, bh2, bh3, bl0, bl1, bl2, bl3;
                LDSM_X4(bh0, bh1, bh2, bh3, ukh + koff);
                LDSM_X4(bl0, bl1, bl2, bl3, ukl + koff);
                mma16(s[2 * ntp],     qfh[ks], bh0, bh1);
                mma16(s[2 * ntp],     qfh[ks], bl0, bl1);
                mma16(s[2 * ntp],     qfl[ks], bh0, bh1);
                mma16(s[2 * ntp + 1], qfh[ks], bh2, bh3);
                mma16(s[2 * ntp + 1], qfh[ks], bl2, bl3);
                mma16(s[2 * ntp + 1], qfl[ks], bh2, bh3);
            }
        }

        float mx0 = -1e30f, mx8 = -1e30f;
#pragma unroll
        for (int nt = 0; nt < 8; nt++) {
            int kd0 = kdoc[nt * 8 + 2 * t], kd1 = kdoc[nt * 8 + 2 * t + 1];
            s[nt][0] = (qd0 == kd0) ? s[nt][0] * ATT_SCALE : -1e30f;
            s[nt][1] = (qd0 == kd1) ? s[nt][1] * ATT_SCALE : -1e30f;
            s[nt][2] = (qd8 == kd0) ? s[nt][2] * ATT_SCALE : -1e30f;
            s[nt][3] = (qd8 == kd1) ? s[nt][3] * ATT_SCALE : -1e30f;
            mx0 = fmaxf(mx0, fmaxf(s[nt][0], s[nt][1]));
            mx8 = fmaxf(mx8, fmaxf(s[nt][2], s[nt][3]));
        }
        mx0 = fmaxf(mx0, __shfl_xor_sync(0xffffffffu, mx0, 1));
        mx0 = fmaxf(mx0, __shfl_xor_sync(0xffffffffu, mx0, 2));
        mx8 = fmaxf(mx8, __shfl_xor_sync(0xffffffffu, mx8, 1));
        mx8 = fmaxf(mx8, __shfl_xor_sync(0xffffffffu, mx8, 2));
        const float mn0 = fmaxf(m0, mx0), mn8 = fmaxf(m8, mx8);
        const float f0 = __expf(m0 - mn0), f8 = __expf(m8 - mn8);
        float sum0 = 0.f, sum8 = 0.f;
#pragma unroll
        for (int nt = 0; nt < 8; nt++) {
            s[nt][0] = (s[nt][0] > -1e29f) ? __expf(s[nt][0] - mn0) : 0.f;
            s[nt][1] = (s[nt][1] > -1e29f) ? __expf(s[nt][1] - mn0) : 0.f;
            s[nt][2] = (s[nt][2] > -1e29f) ? __expf(s[nt][2] - mn8) : 0.f;
            s[nt][3] = (s[nt][3] > -1e29f) ? __expf(s[nt][3] - mn8) : 0.f;
            sum0 += s[nt][0] + s[nt][1];
            sum8 += s[nt][2] + s[nt][3];
        }
        sum0 += __shfl_xor_sync(0xffffffffu, sum0, 1);
        sum0 += __shfl_xor_sync(0xffffffffu, sum0, 2);
        sum8 += __shfl_xor_sync(0xffffffffu, sum8, 1);
        sum8 += __shfl_xor_sync(0xffffffffu, sum8, 2);
        l0 = l0 * f0 + sum0;  l8 = l8 * f8 + sum8;
        m0 = mn0;             m8 = mn8;
#pragma unroll
        for (int nt = 0; nt < 8; nt++) {
            o[nt][0] *= f0; o[nt][1] *= f0;
            o[nt][2] *= f8; o[nt][3] *= f8;
        }

        // O += P V (3-split)
#pragma unroll
        for (int ks = 0; ks < 4; ks++) {
            uint32_t pah[4], pal[4];
            pack_hl(pah[0], pal[0], s[2 * ks][0],     s[2 * ks][1]);
            pack_hl(pah[1], pal[1], s[2 * ks][2],     s[2 * ks][3]);
            pack_hl(pah[2], pal[2], s[2 * ks + 1][0], s[2 * ks + 1][1]);
            pack_hl(pah[3], pal[3], s[2 * ks + 1][2], s[2 * ks + 1][3]);
            uint32_t rowoff = (uint32_t)(ks * 16 * AST * 2) + lmoff;
#pragma unroll
            for (int dg = 0; dg < 4; dg++) {
                uint32_t addr = rowoff + (uint32_t)(dg * 16 * 2);
                uint32_t h0, h1, h2, h3, L0, L1, L2, L3;
                LDSM_X4_T(h0, h1, h2, h3, uvh + addr);
                LDSM_X4_T(L0, L1, L2, L3, uvl + addr);
                mma16(o[2 * dg],     pah, h0, h1);
                mma16(o[2 * dg],     pal, h0, h1);
                mma16(o[2 * dg],     pah, L0, L1);
                mma16(o[2 * dg + 1], pah, h2, h3);
                mma16(o[2 * dg + 1], pal, h2, h3);
                mma16(o[2 * dg + 1], pah, L2, L3);
            }
        }
        __syncthreads();
    }

    const float inv0 = 1.f / l0, inv8 = 1.f / l8;
    const size_t ob0 = rowbase + (size_t)(wrow + g) * Dn;
    const size_t ob8 = rowbase + (size_t)(wrow + g + 8) * Dn;
#pragma unroll
    for (int nt = 0; nt < 8; nt++) {
        int c = nt * 8 + 2 * t;
        uint32_t h0, l0r, h1, l1r;
        pack_hl(h0, l0r, o[nt][0] * inv0, o[nt][1] * inv0);
        pack_hl(h1, l1r, o[nt][2] * inv8, o[nt][3] * inv8);
        *(uint32_t*)&aoh[ob0 + c] = h0;
        *(uint32_t*)&aol[ob0 + c] = l0r;
        *(uint32_t*)&aoh[ob8 + c] = h1;
        *(uint32_t*)&aol[ob8 + c] = l1r;
    }
}

// ---------------------------------------------------------------------------
extern "C" void kernel_launch(void* const* d_in, const int* in_sizes, int n_in,
                              void* d_out, int out_size)
{
    (void)in_sizes; (void)n_in; (void)out_size;
    const float* x  = (const float*)d_in[0];
    const float* wq = (const float*)d_in[1];
    const float* bq = (const float*)d_in[2];
    const float* wk = (const float*)d_in[3];
    const float* bk = (const float*)d_in[4];
    const float* wv = (const float*)d_in[5];
    const float* bv = (const float*)d_in[6];
    const float* wo = (const float*)d_in[7];
    const float* bo = (const float*)d_in[8];
    const int*  doc = (const int*)d_in[9];
    float* out = (float*)d_out;

    __nv_bfloat16 *xh, *xl, *wqh, *wql, *wkh, *wkl, *wvh, *wvl, *woh, *wol;
    __nv_bfloat16 *qh, *ql, *kh, *kl, *vh, *vl, *aoh, *aol;
    cudaGetSymbolAddress((void**)&xh, g_xh);   cudaGetSymbolAddress((void**)&xl, g_xl);
    cudaGetSymbolAddress((void**)&wqh, g_wqh); cudaGetSymbolAddress((void**)&wql, g_wql);
    cudaGetSymbolAddress((void**)&wkh, g_wkh); cudaGetSymbolAddress((void**)&wkl, g_wkl);
    cudaGetSymbolAddress((void**)&wvh, g_wvh); cudaGetSymbolAddress((void**)&wvl, g_wvl);
    cudaGetSymbolAddress((void**)&woh, g_woh); cudaGetSymbolAddress((void**)&wol, g_wol);
    cudaGetSymbolAddress((void**)&qh, g_qh);   cudaGetSymbolAddress((void**)&ql, g_ql);
    cudaGetSymbolAddress((void**)&kh, g_kh);   cudaGetSymbolAddress((void**)&kl, g_kl);
    cudaGetSymbolAddress((void**)&vh, g_vh);   cudaGetSymbolAddress((void**)&vl, g_vl);
    cudaGetSymbolAddress((void**)&aoh, g_aoh); cudaGetSymbolAddress((void**)&aol, g_aol);

    const int nX4 = Mn * Dn / 4, nW4 = Dn * Dn / 4;
    split_bf16<<<(nX4 + 255) / 256, 256>>>((const float4*)x,
        (__nv_bfloat162*)xh, (__nv_bfloat162*)xl, nX4);
    dim3 gw((nW4 + 255) / 256, 4);
    split_w4<<<gw, 256>>>((const float4*)wq, (const float4*)wk,
        (const float4*)wv, (const float4*)wo,
        (__nv_bfloat162*)wqh, (__nv_bfloat162*)wql,
        (__nv_bfloat162*)wkh, (__nv_bfloat162*)wkl,
        (__nv_bfloat162*)wvh, (__nv_bfloat162*)wvl,
        (__nv_bfloat162*)woh, (__nv_bfloat162*)wol, nW4);

    const int gemm_smem = 8 * STAGE * (int)sizeof(__nv_bfloat16);  // 81920
    cudaFuncSetAttribute(gemm_uni, cudaFuncAttributeMaxDynamicSharedMemorySize, gemm_smem);

    // fused QKV
    dim3 ggq(24, Mn / 128);
    gemm_uni<<<ggq, 256, gemm_smem>>>(xh, xl,
        wqh, wql, wkh, wkl, wvh, wvl, bq, bk, bv,
        nullptr, qh, ql, kh, kl, vh, vl, Mn, Dn, Dn);

    const int attn_smem = 4 * 64 * AST * (int)sizeof(__nv_bfloat16);
    cudaFuncSetAttribute(attn_mma, cudaFuncAttributeMaxDynamicSharedMemorySize, attn_smem);
    dim3 ga(Sn / 64, Hn, Bn);
    attn_mma<<<ga, 128, attn_smem>>>(qh, ql, kh, kl, vh, vl, doc, aoh, aol);

    // O projection (fp32 out)
    dim3 ggo(8, Mn / 128);
    gemm_uni<<<ggo, 256, gemm_smem>>>(aoh, aol,
        woh, wol, woh, wol, woh, wol, bo, bo, bo,
        out, nullptr, nullptr, nullptr, nullptr, nullptr, nullptr, Mn, Dn, Dn);
}

// round 9
// speedup vs baseline: 2.8710x; 1.0456x over previous
#include <cuda_runtime.h>
#include <cuda_bf16.h>
#include <cstdint>

#define Bn 2
#define Sn 2048
#define Dn 1024
#define Hn 16
#define HDn 64
#define Mn (Bn*Sn)
#define ATT_SCALE 0.125f   /* 64^-0.5 */

// bf16 hi/lo splits
static __device__ __nv_bfloat16 g_xh[(size_t)Mn*Dn],  g_xl[(size_t)Mn*Dn];
static __device__ __nv_bfloat16 g_wqh[(size_t)Dn*Dn], g_wql[(size_t)Dn*Dn];
static __device__ __nv_bfloat16 g_wkh[(size_t)Dn*Dn], g_wkl[(size_t)Dn*Dn];
static __device__ __nv_bfloat16 g_wvh[(size_t)Dn*Dn], g_wvl[(size_t)Dn*Dn];
static __device__ __nv_bfloat16 g_woh[(size_t)Dn*Dn], g_wol[(size_t)Dn*Dn];
static __device__ __nv_bfloat16 g_qh[(size_t)Mn*Dn],  g_ql[(size_t)Mn*Dn];
static __device__ __nv_bfloat16 g_kh[(size_t)Mn*Dn],  g_kl[(size_t)Mn*Dn];
static __device__ __nv_bfloat16 g_vh[(size_t)Mn*Dn],  g_vl[(size_t)Mn*Dn];
static __device__ __nv_bfloat16 g_aoh[(size_t)Mn*Dn], g_aol[(size_t)Mn*Dn];

// ---------------------------------------------------------------------------
// splits
// ---------------------------------------------------------------------------
__device__ __forceinline__ void split1(float4 v, __nv_bfloat162* hi,
                                       __nv_bfloat162* lo, int i) {
    __nv_bfloat16 hx = __float2bfloat16_rn(v.x);
    __nv_bfloat16 hy = __float2bfloat16_rn(v.y);
    __nv_bfloat16 hz = __float2bfloat16_rn(v.z);
    __nv_bfloat16 hw = __float2bfloat16_rn(v.w);
    hi[2 * i]     = __nv_bfloat162(hx, hy);
    hi[2 * i + 1] = __nv_bfloat162(hz, hw);
    lo[2 * i]     = __nv_bfloat162(__float2bfloat16_rn(v.x - __bfloat162float(hx)),
                                   __float2bfloat16_rn(v.y - __bfloat162float(hy)));
    lo[2 * i + 1] = __nv_bfloat162(__float2bfloat16_rn(v.z - __bfloat162float(hz)),
                                   __float2bfloat16_rn(v.w - __bfloat162float(hw)));
}

__global__ __launch_bounds__(256) void split_bf16(const float4* __restrict__ src,
    __nv_bfloat162* __restrict__ hi, __nv_bfloat162* __restrict__ lo, int n4)
{
    int i = blockIdx.x * 256 + threadIdx.x;
    if (i >= n4) return;
    split1(src[i], hi, lo, i);
}

__global__ __launch_bounds__(256) void split_w4(
    const float4* __restrict__ s0, const float4* __restrict__ s1,
    const float4* __restrict__ s2, const float4* __restrict__ s3,
    __nv_bfloat162* __restrict__ h0, __nv_bfloat162* __restrict__ l0,
    __nv_bfloat162* __restrict__ h1, __nv_bfloat162* __restrict__ l1,
    __nv_bfloat162* __restrict__ h2, __nv_bfloat162* __restrict__ l2,
    __nv_bfloat162* __restrict__ h3, __nv_bfloat162* __restrict__ l3, int n4)
{
    int i = blockIdx.x * 256 + threadIdx.x;
    if (i >= n4) return;
    int w = blockIdx.y;
    const float4* s = (w == 0) ? s0 : (w == 1) ? s1 : (w == 2) ? s2 : s3;
    __nv_bfloat162* h = (w == 0) ? h0 : (w == 1) ? h1 : (w == 2) ? h2 : h3;
    __nv_bfloat162* l = (w == 0) ? l0 : (w == 1) ? l1 : (w == 2) ? l2 : l3;
    split1(s[i], h, l, i);
}

// ---------------------------------------------------------------------------
// helpers
// ---------------------------------------------------------------------------
__device__ __forceinline__ uint32_t s2u(const void* p) {
    return (uint32_t)__cvta_generic_to_shared(p);
}

__device__ __forceinline__ void mma16(float* d, const uint32_t* a,
                                      uint32_t b0, uint32_t b1) {
    asm volatile(
        "mma.sync.aligned.m16n8k16.row.col.f32.bf16.bf16.f32 "
        "{%0,%1,%2,%3},{%4,%5,%6,%7},{%8,%9},{%0,%1,%2,%3};"
        : "+f"(d[0]), "+f"(d[1]), "+f"(d[2]), "+f"(d[3])
        : "r"(a[0]), "r"(a[1]), "r"(a[2]), "r"(a[3]), "r"(b0), "r"(b1));
}

__device__ __forceinline__ void cp16(uint32_t s, const void* g) {
    asm volatile("cp.async.cg.shared.global [%0], [%1], 16;" :: "r"(s), "l"(g));
}

__device__ __forceinline__ void pack_hl(uint32_t& hi, uint32_t& lo, float a, float b) {
    __nv_bfloat162 h = __float22bfloat162_rn(make_float2(a, b));
    float2 hf = __bfloat1622float2(h);
    __nv_bfloat162 l = __float22bfloat162_rn(make_float2(a - hf.x, b - hf.y));
    hi = *(uint32_t*)&h; lo = *(uint32_t*)&l;
}

#define LDSM_X4(r0,r1,r2,r3, addr) \
    asm volatile("ldmatrix.sync.aligned.m8n8.x4.shared.b16 {%0,%1,%2,%3}, [%4];" \
        : "=r"(r0), "=r"(r1), "=r"(r2), "=r"(r3) : "r"(addr))

#define LDSM_X4_T(r0,r1,r2,r3, addr) \
    asm volatile("ldmatrix.sync.aligned.m8n8.x4.trans.shared.b16 {%0,%1,%2,%3}, [%4];" \
        : "=r"(r0), "=r"(r1), "=r"(r2), "=r"(r3) : "r"(addr))

// ---------------------------------------------------------------------------
// 3xBF16 tensor-core GEMM (unified QKV / O). Block 128x128, KT=32, cp.async
// double-buffered, ldmatrix frags, term-major MMA order (RAW distance 8).
// ---------------------------------------------------------------------------
#define KT 32
#define PAD 40
#define STAGE (128 * PAD)

__global__ __launch_bounds__(256, 2) void gemm_uni(
    const __nv_bfloat16* __restrict__ Ah, const __nv_bfloat16* __restrict__ Al,
    const __nv_bfloat16* __restrict__ Bh0, const __nv_bfloat16* __restrict__ Bl0,
    const __nv_bfloat16* __restrict__ Bh1, const __nv_bfloat16* __restrict__ Bl1,
    const __nv_bfloat16* __restrict__ Bh2, const __nv_bfloat16* __restrict__ Bl2,
    const float* __restrict__ bias0, const float* __restrict__ bias1,
    const float* __restrict__ bias2,
    float* __restrict__ C,
    __nv_bfloat16* __restrict__ Ch0, __nv_bfloat16* __restrict__ Cl0,
    __nv_bfloat16* __restrict__ Ch1, __nv_bfloat16* __restrict__ Cl1,
    __nv_bfloat16* __restrict__ Ch2, __nv_bfloat16* __restrict__ Cl2,
    int M, int N, int K)
{
    extern __shared__ char dynsmem[];
    __nv_bfloat16* sm = (__nv_bfloat16*)dynsmem;
    __nv_bfloat16* sAh = sm;
    __nv_bfloat16* sAl = sm + 2 * STAGE;
    __nv_bfloat16* sBh = sm + 4 * STAGE;
    __nv_bfloat16* sBl = sm + 6 * STAGE;

    const int wsel = blockIdx.x >> 3;
    const __nv_bfloat16* Bh = (wsel == 0) ? Bh0 : (wsel == 1) ? Bh1 : Bh2;
    const __nv_bfloat16* Bl = (wsel == 0) ? Bl0 : (wsel == 1) ? Bl1 : Bl2;
    const float* bias = (wsel == 0) ? bias0 : (wsel == 1) ? bias1 : bias2;
    __nv_bfloat16* Ch = (wsel == 0) ? Ch0 : (wsel == 1) ? Ch1 : Ch2;
    __nv_bfloat16* Cl = (wsel == 0) ? Cl0 : (wsel == 1) ? Cl1 : Cl2;

    const int m0 = blockIdx.y * 128, n0 = (blockIdx.x & 7) * 128;
    const int tid = threadIdx.x;
    const int lane = tid & 31, wid = tid >> 5;
    const int g = lane >> 2, t = lane & 3;
    const int mBase = (wid & 3) * 32;
    const int nBase = (wid >> 2) * 64;

    const int lrow = tid >> 1;
    const int lcol = (tid & 1) * 16;

    const uint32_t sbase = s2u(sm);
    const uint32_t dAh = sbase + (uint32_t)(lrow * PAD + lcol) * 2;
    const uint32_t dAl = dAh + 2 * STAGE * 2;
    const uint32_t dBh = dAh + 4 * STAGE * 2;
    const uint32_t dBl = dAh + 6 * STAGE * 2;
    const __nv_bfloat16* gAh = Ah + (size_t)(m0 + lrow) * K + lcol;
    const __nv_bfloat16* gAl = Al + (size_t)(m0 + lrow) * K + lcol;
    const __nv_bfloat16* gBh = Bh + (size_t)(n0 + lrow) * K + lcol;
    const __nv_bfloat16* gBl = Bl + (size_t)(n0 + lrow) * K + lcol;

    const int arow = lane & 15;
    const int acol = (lane >> 4) << 3;
    const int brow = (lane & 7) + ((lane >> 4) << 3);
    const int bcol = ((lane >> 3) & 1) << 3;

    float acc[2][8][4];
#pragma unroll
    for (int i = 0; i < 2; i++)
#pragma unroll
        for (int j = 0; j < 8; j++)
#pragma unroll
            for (int l = 0; l < 4; l++) acc[i][j][l] = 0.f;

    const int nTiles = K / KT;

    auto issue = [&](int kt, int buf) {
        uint32_t so = (uint32_t)(buf * STAGE * 2);
#pragma unroll
        for (int c = 0; c < 2; c++) {
            cp16(dAh + so + c * 16, gAh + kt + c * 8);
            cp16(dAl + so + c * 16, gAl + kt + c * 8);
            cp16(dBh + so + c * 16, gBh + kt + c * 8);
            cp16(dBl + so + c * 16, gBl + kt + c * 8);
        }
        asm volatile("cp.async.commit_group;");
    };

    issue(0, 0);

    for (int tt = 0; tt < nTiles; tt++) {
        const int buf = tt & 1;
        if (tt + 1 < nTiles) {
            issue((tt + 1) * KT, buf ^ 1);
            asm volatile("cp.async.wait_group 1;");
        } else {
            asm volatile("cp.async.wait_group 0;");
        }
        __syncthreads();

        const uint32_t uAh = s2u(sAh + buf * STAGE);
        const uint32_t uAl = s2u(sAl + buf * STAGE);
        const uint32_t uBh = s2u(sBh + buf * STAGE);
        const uint32_t uBl = s2u(sBl + buf * STAGE);

#pragma unroll
        for (int k16 = 0; k16 < KT; k16 += 16) {
            uint32_t ah[2][4], al[2][4];
#pragma unroll
            for (int mt = 0; mt < 2; mt++) {
                uint32_t aoff = (uint32_t)(((mBase + mt * 16 + arow) * PAD + k16 + acol) * 2);
                LDSM_X4(ah[mt][0], ah[mt][1], ah[mt][2], ah[mt][3], uAh + aoff);
                LDSM_X4(al[mt][0], al[mt][1], al[mt][2], al[mt][3], uAl + aoff);
            }
            // process n-tile pairs; within a pair issue term-major so the
            // same accumulator recurs only every 8 MMAs (RAW distance 8)
#pragma unroll
            for (int np = 0; np < 2; np++) {
                uint32_t bh[2][4], bl[2][4];
#pragma unroll
                for (int q = 0; q < 2; q++) {
                    uint32_t boff = (uint32_t)(((nBase + (np * 2 + q) * 16 + brow) * PAD + k16 + bcol) * 2);
                    LDSM_X4(bh[q][0], bh[q][1], bh[q][2], bh[q][3], uBh + boff);
                    LDSM_X4(bl[q][0], bl[q][1], bl[q][2], bl[q][3], uBl + boff);
                }
                // hi*hi (8 distinct accs)
#pragma unroll
                for (int q = 0; q < 2; q++)
#pragma unroll
                    for (int mt = 0; mt < 2; mt++) {
                        mma16(acc[mt][4 * np + 2 * q],     ah[mt], bh[q][0], bh[q][1]);
                        mma16(acc[mt][4 * np + 2 * q + 1], ah[mt], bh[q][2], bh[q][3]);
                    }
                // hi*lo
#pragma unroll
                for (int q = 0; q < 2; q++)
#pragma unroll
                    for (int mt = 0; mt < 2; mt++) {
                        mma16(acc[mt][4 * np + 2 * q],     ah[mt], bl[q][0], bl[q][1]);
                        mma16(acc[mt][4 * np + 2 * q + 1], ah[mt], bl[q][2], bl[q][3]);
                    }
                // lo*hi
#pragma unroll
                for (int q = 0; q < 2; q++)
#pragma unroll
                    for (int mt = 0; mt < 2; mt++) {
                        mma16(acc[mt][4 * np + 2 * q],     al[mt], bh[q][0], bh[q][1]);
                        mma16(acc[mt][4 * np + 2 * q + 1], al[mt], bh[q][2], bh[q][3]);
                    }
            }
        }
        __syncthreads();
    }

#pragma unroll
    for (int mt = 0; mt < 2; mt++) {
        int r0 = m0 + mBase + mt * 16 + g;
#pragma unroll
        for (int nt = 0; nt < 8; nt++) {
            int c = n0 + nBase + nt * 8 + 2 * t;
            float b0v = bias[c], b1v = bias[c + 1];
            float v00 = acc[mt][nt][0] + b0v, v01 = acc[mt][nt][1] + b1v;
            float v10 = acc[mt][nt][2] + b0v, v11 = acc[mt][nt][3] + b1v;
            if (C) {
                *(float2*)&C[(size_t)r0 * N + c] = make_float2(v00, v01);
                *(float2*)&C[(size_t)(r0 + 8) * N + c] = make_float2(v10, v11);
            } else {
                uint32_t h0, l0, h1, l1;
                pack_hl(h0, l0, v00, v01);
                pack_hl(h1, l1, v10, v11);
                *(uint32_t*)&Ch[(size_t)r0 * N + c] = h0;
                *(uint32_t*)&Cl[(size_t)r0 * N + c] = l0;
                *(uint32_t*)&Ch[(size_t)(r0 + 8) * N + c] = h1;
                *(uint32_t*)&Cl[(size_t)(r0 + 8) * N + c] = l1;
            }
        }
    }
}

// ---------------------------------------------------------------------------
// Tensor-core flash attention, doc-block mask + KV range skipping.
// Term-major MMA order (RAW distance 4), cp.async KV staging.
// ---------------------------------------------------------------------------
#define AST 72

__global__ __launch_bounds__(128, 3) void attn_mma(
    const __nv_bfloat16* __restrict__ gqh, const __nv_bfloat16* __restrict__ gql,
    const __nv_bfloat16* __restrict__ gkh, const __nv_bfloat16* __restrict__ gkl,
    const __nv_bfloat16* __restrict__ gvh, const __nv_bfloat16* __restrict__ gvl,
    const int* __restrict__ doc,
    __nv_bfloat16* __restrict__ aoh, __nv_bfloat16* __restrict__ aol)
{
    extern __shared__ char dynsmem[];
    __nv_bfloat16* sKh = (__nv_bfloat16*)dynsmem;
    __nv_bfloat16* sKl = sKh + 64 * AST;
    __nv_bfloat16* sVh = sKl + 64 * AST;
    __nv_bfloat16* sVl = sVh + 64 * AST;
    __shared__ int qdoc[64], kdoc[64], srange[2];

    const int q0 = blockIdx.x * 64;
    const int h = blockIdx.y, b = blockIdx.z;
    const int tid = threadIdx.x;
    const int lane = tid & 31, w = tid >> 5;
    const int g = lane >> 2, t = lane & 3;
    const int wrow = w * 16;

    if (tid == 0) { srange[0] = Sn; srange[1] = 0; }
    if (tid < 64) qdoc[tid] = doc[q0 + tid];
    __syncthreads();
    const int dlo = qdoc[0], dhi = qdoc[63];
    for (int i = tid; i < Sn; i += 128) {
        int di = doc[i];
        if (di == dlo) atomicMin(&srange[0], i);
        if (di == dhi) atomicMax(&srange[1], i);
    }

    const size_t rowbase = (size_t)(b * Sn + q0) * Dn + h * HDn;
    uint32_t qfh[4][4], qfl[4][4];
    {
        const size_t r0 = rowbase + (size_t)(wrow + g) * Dn + 2 * t;
        const size_t r8 = rowbase + (size_t)(wrow + g + 8) * Dn + 2 * t;
#pragma unroll
        for (int ks = 0; ks < 4; ks++) {
            int c = ks * 16;
            qfh[ks][0] = *(const uint32_t*)&gqh[r0 + c];
            qfh[ks][1] = *(const uint32_t*)&gqh[r8 + c];
            qfh[ks][2] = *(const uint32_t*)&gqh[r0 + c + 8];
            qfh[ks][3] = *(const uint32_t*)&gqh[r8 + c + 8];
            qfl[ks][0] = *(const uint32_t*)&gql[r0 + c];
            qfl[ks][1] = *(const uint32_t*)&gql[r8 + c];
            qfl[ks][2] = *(const uint32_t*)&gql[r0 + c + 8];
            qfl[ks][3] = *(const uint32_t*)&gql[r8 + c + 8];
        }
    }
    __syncthreads();   // srange ready

    const int qd0 = qdoc[wrow + g], qd8 = qdoc[wrow + g + 8];
    const int kv_begin = (srange[0] / 64) * 64;
    const int kv_end   = srange[1] + 1;

    const uint32_t ukh = s2u(sKh), ukl = s2u(sKl);
    const uint32_t uvh = s2u(sVh), uvl = s2u(sVl);
    const int brow = (lane & 7) + ((lane >> 4) << 3);
    const int bcol = ((lane >> 3) & 1) << 3;
    const uint32_t lmoff = (uint32_t)(((lane & 15) * AST + ((lane >> 4) << 3)) * 2);

    float o[8][4];
#pragma unroll
    for (int i = 0; i < 8; i++)
#pragma unroll
        for (int j = 0; j < 4; j++) o[i][j] = 0.f;
    float m0 = -1e30f, m8 = -1e30f, l0 = 0.f, l8 = 0.f;

    for (int k0 = kv_begin; k0 < kv_end; k0 += 64) {
        const size_t kb = (size_t)(b * Sn + k0) * Dn + h * HDn;
        // cp.async KV staging (4 x 16B per thread per array)
#pragma unroll
        for (int v = 0; v < 4; v++) {
            int e = tid + v * 128;
            int r = e >> 3, cg = (e & 7) * 8;
            size_t src = kb + (size_t)r * Dn + cg;
            uint32_t dst = (uint32_t)((r * AST + cg) * 2);
            cp16(ukh + dst, gkh + src);
            cp16(ukl + dst, gkl + src);
            cp16(uvh + dst, gvh + src);
            cp16(uvl + dst, gvl + src);
        }
        asm volatile("cp.async.commit_group;");
        if (tid < 64) kdoc[tid] = doc[k0 + tid];
        asm volatile("cp.async.wait_group 0;" ::: "memory");
        __syncthreads();

        // S = Q K^T (3-split), term-major per n-pair (RAW distance 4)
        float s[8][4];
#pragma unroll
        for (int i = 0; i < 8; i++)
#pragma unroll
            for (int j = 0; j < 4; j++) s[i][j] = 0.f;
#pragma unroll
        for (int ks = 0; ks < 4; ks++) {
#pragma unroll
            for (int np = 0; np < 2; np++) {
                uint32_t bh[2][4], bl[2][4];
#pragma unroll
                for (int q = 0; q < 2; q++) {
                    uint32_t koff = (uint32_t)((((np * 2 + q) * 16 + brow) * AST + ks * 16 + bcol) * 2);
                    LDSM_X4(bh[q][0], bh[q][1], bh[q][2], bh[q][3], ukh + koff);
                    LDSM_X4(bl[q][0], bl[q][1], bl[q][2], bl[q][3], ukl + koff);
                }
#pragma unroll
                for (int q = 0; q < 2; q++) {
                    mma16(s[4 * np + 2 * q],     qfh[ks], bh[q][0], bh[q][1]);
                    mma16(s[4 * np + 2 * q + 1], qfh[ks], bh[q][2], bh[q][3]);
                }
#pragma unroll
                for (int q = 0; q < 2; q++) {
                    mma16(s[4 * np + 2 * q],     qfh[ks], bl[q][0], bl[q][1]);
                    mma16(s[4 * np + 2 * q + 1], qfh[ks], bl[q][2], bl[q][3]);
                }
#pragma unroll
                for (int q = 0; q < 2; q++) {
                    mma16(s[4 * np + 2 * q],     qfl[ks], bh[q][0], bh[q][1]);
                    mma16(s[4 * np + 2 * q + 1], qfl[ks], bh[q][2], bh[q][3]);
                }
            }
        }

        float mx0 = -1e30f, mx8 = -1e30f;
#pragma unroll
        for (int nt = 0; nt < 8; nt++) {
            int kd0 = kdoc[nt * 8 + 2 * t], kd1 = kdoc[nt * 8 + 2 * t + 1];
            s[nt][0] = (qd0 == kd0) ? s[nt][0] * ATT_SCALE : -1e30f;
            s[nt][1] = (qd0 == kd1) ? s[nt][1] * ATT_SCALE : -1e30f;
            s[nt][2] = (qd8 == kd0) ? s[nt][2] * ATT_SCALE : -1e30f;
            s[nt][3] = (qd8 == kd1) ? s[nt][3] * ATT_SCALE : -1e30f;
            mx0 = fmaxf(mx0, fmaxf(s[nt][0], s[nt][1]));
            mx8 = fmaxf(mx8, fmaxf(s[nt][2], s[nt][3]));
        }
        mx0 = fmaxf(mx0, __shfl_xor_sync(0xffffffffu, mx0, 1));
        mx0 = fmaxf(mx0, __shfl_xor_sync(0xffffffffu, mx0, 2));
        mx8 = fmaxf(mx8, __shfl_xor_sync(0xffffffffu, mx8, 1));
        mx8 = fmaxf(mx8, __shfl_xor_sync(0xffffffffu, mx8, 2));
        const float mn0 = fmaxf(m0, mx0), mn8 = fmaxf(m8, mx8);
        const float f0 = __expf(m0 - mn0), f8 = __expf(m8 - mn8);
        float sum0 = 0.f, sum8 = 0.f;
#pragma unroll
        for (int nt = 0; nt < 8; nt++) {
            s[nt][0] = (s[nt][0] > -1e29f) ? __expf(s[nt][0] - mn0) : 0.f;
            s[nt][1] = (s[nt][1] > -1e29f) ? __expf(s[nt][1] - mn0) : 0.f;
            s[nt][2] = (s[nt][2] > -1e29f) ? __expf(s[nt][2] - mn8) : 0.f;
            s[nt][3] = (s[nt][3] > -1e29f) ? __expf(s[nt][3] - mn8) : 0.f;
            sum0 += s[nt][0] + s[nt][1];
            sum8 += s[nt][2] + s[nt][3];
        }
        sum0 += __shfl_xor_sync(0xffffffffu, sum0, 1);
        sum0 += __shfl_xor_sync(0xffffffffu, sum0, 2);
        sum8 += __shfl_xor_sync(0xffffffffu, sum8, 1);
        sum8 += __shfl_xor_sync(0xffffffffu, sum8, 2);
        l0 = l0 * f0 + sum0;  l8 = l8 * f8 + sum8;
        m0 = mn0;             m8 = mn8;
#pragma unroll
        for (int nt = 0; nt < 8; nt++) {
            o[nt][0] *= f0; o[nt][1] *= f0;
            o[nt][2] *= f8; o[nt][3] *= f8;
        }

        // O += P V (3-split), term-major per d-pair (RAW distance 4)
#pragma unroll
        for (int ks = 0; ks < 4; ks++) {
            uint32_t pah[4], pal[4];
            pack_hl(pah[0], pal[0], s[2 * ks][0],     s[2 * ks][1]);
            pack_hl(pah[1], pal[1], s[2 * ks][2],     s[2 * ks][3]);
            pack_hl(pah[2], pal[2], s[2 * ks + 1][0], s[2 * ks + 1][1]);
            pack_hl(pah[3], pal[3], s[2 * ks + 1][2], s[2 * ks + 1][3]);
            uint32_t rowoff = (uint32_t)(ks * 16 * AST * 2) + lmoff;
#pragma unroll
            for (int dp = 0; dp < 2; dp++) {
                uint32_t vh[2][4], vl[2][4];
#pragma unroll
                for (int q = 0; q < 2; q++) {
                    uint32_t addr = rowoff + (uint32_t)((dp * 2 + q) * 16 * 2);
                    LDSM_X4_T(vh[q][0], vh[q][1], vh[q][2], vh[q][3], uvh + addr);
                    LDSM_X4_T(vl[q][0], vl[q][1], vl[q][2], vl[q][3], uvl + addr);
                }
#pragma unroll
                for (int q = 0; q < 2; q++) {
                    mma16(o[4 * dp + 2 * q],     pah, vh[q][0], vh[q][1]);
                    mma16(o[4 * dp + 2 * q + 1], pah, vh[q][2], vh[q][3]);
                }
#pragma unroll
                for (int q = 0; q < 2; q++) {
                    mma16(o[4 * dp + 2 * q],     pal, vh[q][0], vh[q][1]);
                    mma16(o[4 * dp + 2 * q + 1], pal, vh[q][2], vh[q][3]);
                }
#pragma unroll
                for (int q = 0; q < 2; q++) {
                    mma16(o[4 * dp + 2 * q],     pah, vl[q][0], vl[q][1]);
                    mma16(o[4 * dp + 2 * q + 1], pah, vl[q][2], vl[q][3]);
                }
            }
        }
        __syncthreads();
    }

    const float inv0 = 1.f / l0, inv8 = 1.f / l8;
    const size_t ob0 = rowbase + (size_t)(wrow + g) * Dn;
    const size_t ob8 = rowbase + (size_t)(wrow + g + 8) * Dn;
#pragma unroll
    for (int nt = 0; nt < 8; nt++) {
        int c = nt * 8 + 2 * t;
        uint32_t h0, l0r, h1, l1r;
        pack_hl(h0, l0r, o[nt][0] * inv0, o[nt][1] * inv0);
        pack_hl(h1, l1r, o[nt][2] * inv8, o[nt][3] * inv8);
        *(uint32_t*)&aoh[ob0 + c] = h0;
        *(uint32_t*)&aol[ob0 + c] = l0r;
        *(uint32_t*)&aoh[ob8 + c] = h1;
        *(uint32_t*)&aol[ob8 + c] = l1r;
    }
}

// ---------------------------------------------------------------------------
extern "C" void kernel_launch(void* const* d_in, const int* in_sizes, int n_in,
                              void* d_out, int out_size)
{
    (void)in_sizes; (void)n_in; (void)out_size;
    const float* x  = (const float*)d_in[0];
    const float* wq = (const float*)d_in[1];
    const float* bq = (const float*)d_in[2];
    const float* wk = (const float*)d_in[3];
    const float* bk = (const float*)d_in[4];
    const float* wv = (const float*)d_in[5];
    const float* bv = (const float*)d_in[6];
    const float* wo = (const float*)d_in[7];
    const float* bo = (const float*)d_in[8];
    const int*  doc = (const int*)d_in[9];
    float* out = (float*)d_out;

    __nv_bfloat16 *xh, *xl, *wqh, *wql, *wkh, *wkl, *wvh, *wvl, *woh, *wol;
    __nv_bfloat16 *qh, *ql, *kh, *kl, *vh, *vl, *aoh, *aol;
    cudaGetSymbolAddress((void**)&xh, g_xh);   cudaGetSymbolAddress((void**)&xl, g_xl);
    cudaGetSymbolAddress((void**)&wqh, g_wqh); cudaGetSymbolAddress((void**)&wql, g_wql);
    cudaGetSymbolAddress((void**)&wkh, g_wkh); cudaGetSymbolAddress((void**)&wkl, g_wkl);
    cudaGetSymbolAddress((void**)&wvh, g_wvh); cudaGetSymbolAddress((void**)&wvl, g_wvl);
    cudaGetSymbolAddress((void**)&woh, g_woh); cudaGetSymbolAddress((void**)&wol, g_wol);
    cudaGetSymbolAddress((void**)&qh, g_qh);   cudaGetSymbolAddress((void**)&ql, g_ql);
    cudaGetSymbolAddress((void**)&kh, g_kh);   cudaGetSymbolAddress((void**)&kl, g_kl);
    cudaGetSymbolAddress((void**)&vh, g_vh);   cudaGetSymbolAddress((void**)&vl, g_vl);
    cudaGetSymbolAddress((void**)&aoh, g_aoh); cudaGetSymbolAddress((void**)&aol, g_aol);

    const int nX4 = Mn * Dn / 4, nW4 = Dn * Dn / 4;
    split_bf16<<<(nX4 + 255) / 256, 256>>>((const float4*)x,
        (__nv_bfloat162*)xh, (__nv_bfloat162*)xl, nX4);
    dim3 gw((nW4 + 255) / 256, 4);
    split_w4<<<gw, 256>>>((const float4*)wq, (const float4*)wk,
        (const float4*)wv, (const float4*)wo,
        (__nv_bfloat162*)wqh, (__nv_bfloat162*)wql,
        (__nv_bfloat162*)wkh, (__nv_bfloat162*)wkl,
        (__nv_bfloat162*)wvh, (__nv_bfloat162*)wvl,
        (__nv_bfloat162*)woh, (__nv_bfloat162*)wol, nW4);

    const int gemm_smem = 8 * STAGE * (int)sizeof(__nv_bfloat16);  // 81920
    cudaFuncSetAttribute(gemm_uni, cudaFuncAttributeMaxDynamicSharedMemorySize, gemm_smem);

    // fused QKV
    dim3 ggq(24, Mn / 128);
    gemm_uni<<<ggq, 256, gemm_smem>>>(xh, xl,
        wqh, wql, wkh, wkl, wvh, wvl, bq, bk, bv,
        nullptr, qh, ql, kh, kl, vh, vl, Mn, Dn, Dn);

    const int attn_smem = 4 * 64 * AST * (int)sizeof(__nv_bfloat16);
    cudaFuncSetAttribute(attn_mma, cudaFuncAttributeMaxDynamicSharedMemorySize, attn_smem);
    dim3 ga(Sn / 64, Hn, Bn);
    attn_mma<<<ga, 128, attn_smem>>>(qh, ql, kh, kl, vh, vl, doc, aoh, aol);

    // O projection (fp32 out)
    dim3 ggo(8, Mn / 128);
    gemm_uni<<<ggo, 256, gemm_smem>>>(aoh, aol,
        woh, wol, woh, wol, woh, wol, bo, bo, bo,
        out, nullptr, nullptr, nullptr, nullptr, nullptr, nullptr, Mn, Dn, Dn);
}